// round 10
// baseline (speedup 1.0000x reference)
#include <cuda_runtime.h>
#include <cuda_bf16.h>
#include <cstdint>

#define NB 4096
#define ND 1024
#define F_EPS 1e-6f
#define F_MARGIN 0.3f

// ------------------------- scratch (static device globals; no allocation) ---
__device__ float g_G[(size_t)NB * NB];   // gram matrix F F^T (64 MB)
__device__ float g_t[NB];
__device__ float g_c[NB];
__device__ int   g_pos[NB];
__device__ int   g_neg[NB];
__device__ float g_part[NB];
__device__ __align__(16) uint16_t g_hi[(size_t)NB * ND];  // bf16 hi
__device__ __align__(16) uint16_t g_lo[(size_t)NB * ND];  // bf16 lo

// ------------------------- Threefry-2x32 (20 rounds), JAX-compatible --------
__device__ __forceinline__ uint32_t rotl_d(uint32_t x, int r) {
    return __funnelshift_l(x, x, r);
}
__device__ __forceinline__ void tf_enc(uint32_t k0, uint32_t k1,
                                       uint32_t x0, uint32_t x1,
                                       uint32_t& o0, uint32_t& o1) {
    uint32_t k2 = k0 ^ k1 ^ 0x1BD11BDAu;
    x0 += k0; x1 += k1;
#define TFR(R) { x0 += x1; x1 = rotl_d(x1, R); x1 ^= x0; }
    TFR(13) TFR(15) TFR(26) TFR(6)
    x0 += k1; x1 += k2 + 1u;
    TFR(17) TFR(29) TFR(16) TFR(24)
    x0 += k2; x1 += k0 + 2u;
    TFR(13) TFR(15) TFR(26) TFR(6)
    x0 += k0; x1 += k1 + 3u;
    TFR(17) TFR(29) TFR(16) TFR(24)
    x0 += k1; x1 += k2 + 4u;
    TFR(13) TFR(15) TFR(26) TFR(6)
    x0 += k2; x1 += k0 + 5u;
#undef TFR
    o0 = x0; o1 = x1;
}
static inline uint32_t rotl_h(uint32_t x, int r) { return (x << r) | (x >> (32 - r)); }
static void tf_enc_host(uint32_t k0, uint32_t k1, uint32_t x0, uint32_t x1,
                        uint32_t& o0, uint32_t& o1) {
    uint32_t k2 = k0 ^ k1 ^ 0x1BD11BDAu;
    x0 += k0; x1 += k1;
#define TFRH(R) { x0 += x1; x1 = rotl_h(x1, R); x1 ^= x0; }
    TFRH(13) TFRH(15) TFRH(26) TFRH(6)
    x0 += k1; x1 += k2 + 1u;
    TFRH(17) TFRH(29) TFRH(16) TFRH(24)
    x0 += k2; x1 += k0 + 2u;
    TFRH(13) TFRH(15) TFRH(26) TFRH(6)
    x0 += k0; x1 += k1 + 3u;
    TFRH(17) TFRH(29) TFRH(16) TFRH(24)
    x0 += k1; x1 += k2 + 4u;
    TFRH(13) TFRH(15) TFRH(26) TFRH(6)
    x0 += k2; x1 += k0 + 5u;
#undef TFRH
    o0 = x0; o1 = x1;
}

// ------------------------- row norms / sums ---------------------------------
__global__ void __launch_bounds__(256) k_norms(const float* __restrict__ F) {
    const int i = blockIdx.x;
    const float4* row = (const float4*)(F + (size_t)i * ND);
    float n2 = 0.f, s = 0.f;
    for (int k = threadIdx.x; k < ND / 4; k += blockDim.x) {
        float4 v = row[k];
        n2 = fmaf(v.x, v.x, fmaf(v.y, v.y, fmaf(v.z, v.z, fmaf(v.w, v.w, n2))));
        s += (v.x + v.y) + (v.z + v.w);
    }
    for (int off = 16; off; off >>= 1) {
        n2 += __shfl_down_sync(0xffffffffu, n2, off);
        s  += __shfl_down_sync(0xffffffffu, s,  off);
    }
    __shared__ float sn[8], ss[8];
    const int warp = threadIdx.x >> 5, lane = threadIdx.x & 31;
    if (lane == 0) { sn[warp] = n2; ss[warp] = s; }
    __syncthreads();
    if (threadIdx.x == 0) {
        float a = 0.f, b = 0.f;
        for (int w = 0; w < 8; w++) { a += sn[w]; b += ss[w]; }
        g_t[i] = a + 2.f * F_EPS * b + (float)ND * F_EPS * F_EPS;
        g_c[i] = a - 2.f * F_EPS * b;
    }
}

// ------------------------- bf16 hi/lo split (row-major) ---------------------
__global__ void __launch_bounds__(256) k_split(const float* __restrict__ F) {
    const int idx = blockIdx.x * 256 + threadIdx.x;   // 0..524287, 8 floats each
    const size_t e0 = (size_t)idx * 8;
    const float4* src = (const float4*)(F + e0);
    float4 v0 = src[0], v1 = src[1];
    float x[8] = {v0.x, v0.y, v0.z, v0.w, v1.x, v1.y, v1.z, v1.w};
    uint16_t h[8], l[8];
#pragma unroll
    for (int e = 0; e < 8; e++) {
        __nv_bfloat16 hb = __float2bfloat16(x[e]);
        __nv_bfloat16 lb = __float2bfloat16(x[e] - __bfloat162float(hb));
        h[e] = *(uint16_t*)&hb;
        l[e] = *(uint16_t*)&lb;
    }
    *(uint4*)(g_hi + e0) = *(const uint4*)h;
    *(uint4*)(g_lo + e0) = *(const uint4*)l;
}

// ------------------------- mma.sync GEMM helpers ----------------------------
__device__ __forceinline__ uint32_t smem_u32(const void* p) {
    uint32_t a;
    asm("{ .reg .u64 t; cvta.to.shared.u64 t, %1; cvt.u32.u64 %0, t; }"
        : "=r"(a) : "l"(p));
    return a;
}
#define LDSM4(r0, r1, r2, r3, addr)                                          \
    asm volatile("ldmatrix.sync.aligned.m8n8.x4.shared.b16 {%0,%1,%2,%3}, [%4];" \
                 : "=r"(r0), "=r"(r1), "=r"(r2), "=r"(r3) : "r"(addr))
#define MMA16816(c, a0, a1, a2, a3, b0, b1)                                  \
    asm volatile("mma.sync.aligned.m16n8k16.row.col.f32.bf16.bf16.f32 "      \
                 "{%0,%1,%2,%3}, {%4,%5,%6,%7}, {%8,%9}, {%0,%1,%2,%3};"     \
                 : "+f"((c)[0]), "+f"((c)[1]), "+f"((c)[2]), "+f"((c)[3])    \
                 : "r"(a0), "r"(a1), "r"(a2), "r"(a3), "r"(b0), "r"(b1))
#define CP16(saddr, gptr)                                                    \
    asm volatile("cp.async.cg.shared.global [%0], [%1], 16;"                 \
                 :: "r"(saddr), "l"(gptr) : "memory")

// smem stage layout: 4 tiles of 8192 B (Ahi, Alo, Bhi, Blo), 3 stages.
// Each tile: 128 rows x 64 B (32 bf16), 16B chunks swizzled c' = c ^ ((m>>1)&3).
#define STAGE_BYTES 32768
#define TILE_BYTES  8192
#define DSM_BYTES   98304   // 3 stages; also covers 128x132 transpose (67584)

// ------------------------- fused GEMM + sampling ----------------------------
// Grid: 784 blocks in groups of 49 = 33 gemm + 16 sample (interleaved so
// sample CTAs co-reside with gemm CTAs and fill idle issue slots).
__global__ void __launch_bounds__(256, 2) k_gemm_sample(
    const int* __restrict__ labels,
    uint32_t k1a, uint32_t k1b, uint32_t k2a, uint32_t k2b) {
    extern __shared__ char dsm[];
    const int tid = threadIdx.x;
    const int lane = tid & 31, wid = tid >> 5;

    const int grp = blockIdx.x / 49, rem = blockIdx.x % 49;

    if (rem >= 33) {
        // ======================= sampling branch ============================
        const int sidx = grp * 16 + (rem - 33);   // 0..255, 16 rows each
        int* slab = (int*)dsm;
        for (int t = tid * 4; t < NB; t += 256 * 4)
            *(int4*)&slab[t] = *(const int4*)&labels[t];
        __syncthreads();
#pragma unroll 1
        for (int rr = 0; rr < 2; rr++) {
            const int i = sidx * 16 + wid * 2 + rr;
            const int Li = slab[i];
            const uint32_t base = (uint32_t)i << 12;
            unsigned long long bestn = 0ull, bestp = 0ull;
#pragma unroll 1
            for (int j = lane; j < NB; j += 32) {
                uint32_t o0, o1;
                tf_enc(k2a, k2b, 0u, base + (uint32_t)j, o0, o1);
                uint32_t v = ((o0 ^ o1) >> 9) + 1u;
                unsigned long long cand =
                    ((unsigned long long)v << 12) | (uint32_t)(4095 - j);
                if (slab[j] != Li) {
                    if (cand > bestn) bestn = cand;
                } else {
                    uint32_t p0, p1;
                    tf_enc(k1a, k1b, 0u, base + (uint32_t)j, p0, p1);
                    uint32_t vp = ((p0 ^ p1) >> 9) + 1u;
                    unsigned long long candp =
                        ((unsigned long long)vp << 12) | (uint32_t)(4095 - j);
                    if (candp > bestp) bestp = candp;
                }
            }
            for (int off = 16; off; off >>= 1) {
                unsigned long long a = __shfl_down_sync(0xffffffffu, bestn, off);
                unsigned long long b = __shfl_down_sync(0xffffffffu, bestp, off);
                if (a > bestn) bestn = a;
                if (b > bestp) bestp = b;
            }
            if (lane == 0) {
                g_neg[i] = 4095 - (int)(bestn & 0xFFFu);
                g_pos[i] = 4095 - (int)(bestp & 0xFFFu);
            }
        }
        return;
    }

    // =========================== GEMM branch ================================
    const int gid = grp * 33 + rem;               // 0..527 triangle tile
    int bx = (int)((sqrt(8.0 * (double)gid + 1.0) - 1.0) * 0.5);
    while ((bx + 1) * (bx + 2) / 2 <= gid) bx++;
    while (bx * (bx + 1) / 2 > gid) bx--;
    int by = gid - bx * (bx + 1) / 2;

    const uint32_t smemBase = smem_u32(dsm);
    const int wm = wid >> 2, wn = wid & 3;   // warp tile: 64(m) x 32(n)

    const uint16_t* gsrc[4];
    gsrc[0] = g_hi + (size_t)(bx * 128) * ND;
    gsrc[1] = g_lo + (size_t)(bx * 128) * ND;
    gsrc[2] = g_hi + (size_t)(by * 128) * ND;
    gsrc[3] = g_lo + (size_t)(by * 128) * ND;

    float acc[4][4][4];
#pragma unroll
    for (int a = 0; a < 4; a++)
#pragma unroll
        for (int b = 0; b < 4; b++)
#pragma unroll
            for (int c = 0; c < 4; c++) acc[a][b][c] = 0.f;

#define LOAD_STAGE(S, KT)                                                     \
    {                                                                         \
        _Pragma("unroll")                                                     \
        for (int i = 0; i < 8; i++) {                                         \
            int idx = tid + i * 256;                                          \
            int tile = idx >> 9;                                              \
            int m = (idx >> 2) & 127;                                         \
            int c = idx & 3;                                                  \
            const uint16_t* gp = gsrc[tile] + (size_t)m * ND + (KT) + c * 8;  \
            uint32_t sa = smemBase + (uint32_t)(S) * STAGE_BYTES +            \
                          tile * TILE_BYTES + m * 64 +                        \
                          ((c ^ ((m >> 1) & 3)) * 16);                        \
            CP16(sa, gp);                                                     \
        }                                                                     \
    }

    LOAD_STAGE(0, 0)
    asm volatile("cp.async.commit_group;" ::: "memory");
    LOAD_STAGE(1, 32)
    asm volatile("cp.async.commit_group;" ::: "memory");

    const int r15 = lane & 15, kh = lane >> 4;
    const uint32_t rA = (uint32_t)(wm * 64 + r15);
    const uint32_t rB = (uint32_t)(wn * 32 + r15);
    const uint32_t swA = (rA >> 1) & 3, swB = (rB >> 1) & 3;

    int stC = 0, stP = 2;
#pragma unroll 1
    for (int kc = 0; kc < 32; kc++) {
        asm volatile("cp.async.wait_group 1;" ::: "memory");
        __syncthreads();
        if (kc + 2 < 32) LOAD_STAGE(stP, (kc + 2) * 32)
        asm volatile("cp.async.commit_group;" ::: "memory");

        const uint32_t sb = smemBase + (uint32_t)stC * STAGE_BYTES;
        const uint32_t aH = sb, aL = sb + TILE_BYTES;
        const uint32_t bH = sb + 2 * TILE_BYTES, bL = sb + 3 * TILE_BYTES;

#pragma unroll
        for (int k16 = 0; k16 < 2; k16++) {
            const uint32_t cIdx = (uint32_t)(k16 * 2 + kh);
            const uint32_t cpA = (cIdx ^ swA) * 16u;
            const uint32_t cpB = (cIdx ^ swB) * 16u;
            // --- B fragments (4 LDSM) ---
            uint32_t bh[4][2], bl[4][2];
            {
                uint32_t r0, r1, r2, r3;
                LDSM4(r0, r1, r2, r3, bH + rB * 64 + cpB);
                bh[0][0] = r0; bh[1][0] = r1; bh[0][1] = r2; bh[1][1] = r3;
                LDSM4(r0, r1, r2, r3, bH + (rB + 16) * 64 + cpB);
                bh[2][0] = r0; bh[3][0] = r1; bh[2][1] = r2; bh[3][1] = r3;
                LDSM4(r0, r1, r2, r3, bL + rB * 64 + cpB);
                bl[0][0] = r0; bl[1][0] = r1; bl[0][1] = r2; bl[1][1] = r3;
                LDSM4(r0, r1, r2, r3, bL + (rB + 16) * 64 + cpB);
                bl[2][0] = r0; bl[3][0] = r1; bl[2][1] = r2; bl[3][1] = r3;
            }
            // --- A fragments: double-buffered, prefetch mt+1 before MMAs ---
            uint32_t ah[2][4], al[2][4];
            LDSM4(ah[0][0], ah[0][1], ah[0][2], ah[0][3], aH + rA * 64 + cpA);
            LDSM4(al[0][0], al[0][1], al[0][2], al[0][3], aL + rA * 64 + cpA);
#pragma unroll
            for (int mt = 0; mt < 4; mt++) {
                const int cur = mt & 1, nxt = cur ^ 1;
                if (mt < 3) {
                    const uint32_t ra = (rA + (uint32_t)(mt + 1) * 16) * 64;
                    LDSM4(ah[nxt][0], ah[nxt][1], ah[nxt][2], ah[nxt][3],
                          aH + ra + cpA);
                    LDSM4(al[nxt][0], al[nxt][1], al[nxt][2], al[nxt][3],
                          aL + ra + cpA);
                }
#pragma unroll
                for (int nt = 0; nt < 4; nt++)
                    MMA16816(acc[mt][nt], ah[cur][0], ah[cur][1], ah[cur][2],
                             ah[cur][3], bh[nt][0], bh[nt][1]);
#pragma unroll
                for (int nt = 0; nt < 4; nt++)
                    MMA16816(acc[mt][nt], ah[cur][0], ah[cur][1], ah[cur][2],
                             ah[cur][3], bl[nt][0], bl[nt][1]);
#pragma unroll
                for (int nt = 0; nt < 4; nt++)
                    MMA16816(acc[mt][nt], al[cur][0], al[cur][1], al[cur][2],
                             al[cur][3], bh[nt][0], bh[nt][1]);
            }
        }
        stC = (stC == 2) ? 0 : stC + 1;
        stP = (stP == 2) ? 0 : stP + 1;
    }

    // ---------------- epilogue: direct tile + mirror via smem transpose -----
    const int r0 = bx * 128, c0 = by * 128;
    const int qr = lane >> 2, qc = 2 * (lane & 3);
#pragma unroll
    for (int mt = 0; mt < 4; mt++)
#pragma unroll
        for (int nt = 0; nt < 4; nt++) {
            int row = r0 + wm * 64 + mt * 16 + qr;
            int col = c0 + wn * 32 + nt * 8 + qc;
            float2 v01 = make_float2(acc[mt][nt][0], acc[mt][nt][1]);
            float2 v23 = make_float2(acc[mt][nt][2], acc[mt][nt][3]);
            *(float2*)&g_G[(size_t)row * NB + col] = v01;
            *(float2*)&g_G[(size_t)(row + 8) * NB + col] = v23;
        }

    if (bx != by) {
        float (*sT)[132] = (float (*)[132])dsm;   // [n][m], 128x132 floats
        __syncthreads();   // compute buffers dead; reuse smem
#pragma unroll
        for (int mt = 0; mt < 4; mt++)
#pragma unroll
            for (int nt = 0; nt < 4; nt++) {
                int rl = wm * 64 + mt * 16 + qr;
                int cl = wn * 32 + nt * 8 + qc;
                sT[cl][rl]         = acc[mt][nt][0];
                sT[cl + 1][rl]     = acc[mt][nt][1];
                sT[cl][rl + 8]     = acc[mt][nt][2];
                sT[cl + 1][rl + 8] = acc[mt][nt][3];
            }
        __syncthreads();
#pragma unroll
        for (int e = tid * 4; e < 128 * 128; e += 256 * 4) {
            int n = e >> 7, m = e & 127;
            float4 v = *(float4*)&sT[n][m];
            *(float4*)&g_G[(size_t)(c0 + n) * NB + r0 + m] = v;
        }
    }
#undef LOAD_STAGE
}

// ------------------------- loss reduction -----------------------------------
__device__ __forceinline__ float pairterm(float t, float gp, float gq,
                                          float cp, float cq) {
    float sap = fmaxf(fmaf(-2.f, gp, t + cp), 1e-12f);
    float san = fmaxf(fmaf(-2.f, gq, t + cq), 1e-12f);
    float dap, dan;
    asm("sqrt.approx.f32 %0, %1;" : "=f"(dap) : "f"(sap));
    asm("sqrt.approx.f32 %0, %1;" : "=f"(dan) : "f"(san));
    return fmaxf(dap - dan + F_MARGIN, 0.f);
}

__global__ void __launch_bounds__(256) k_loss() {
    const int i = blockIdx.x;
    const int p = g_pos[i], q = g_neg[i];
    const float cp = g_c[p], cq = g_c[q];
    const float4* Gp = (const float4*)(g_G + (size_t)p * NB);
    const float4* Gq = (const float4*)(g_G + (size_t)q * NB);
    const float4* T  = (const float4*)g_t;
    float acc = 0.f;
    for (int j = threadIdx.x; j < NB / 4; j += blockDim.x) {
        float4 gp = Gp[j], gq = Gq[j], tt = T[j];
        acc += pairterm(tt.x, gp.x, gq.x, cp, cq);
        acc += pairterm(tt.y, gp.y, gq.y, cp, cq);
        acc += pairterm(tt.z, gp.z, gq.z, cp, cq);
        acc += pairterm(tt.w, gp.w, gq.w, cp, cq);
    }
    for (int off = 16; off; off >>= 1)
        acc += __shfl_down_sync(0xffffffffu, acc, off);
    __shared__ float sa[8];
    const int warp = threadIdx.x >> 5, lane = threadIdx.x & 31;
    if (lane == 0) sa[warp] = acc;
    __syncthreads();
    if (threadIdx.x == 0) {
        float s = 0.f;
        for (int w = 0; w < 8; w++) s += sa[w];
        g_part[i] = s;
    }
}

__global__ void __launch_bounds__(256) k_final(float* __restrict__ out) {
    __shared__ double sm[256];
    double a = 0.0;
    for (int i = threadIdx.x; i < NB; i += 256) a += (double)g_part[i];
    sm[threadIdx.x] = a;
    __syncthreads();
    for (int s = 128; s; s >>= 1) {
        if (threadIdx.x < s) sm[threadIdx.x] += sm[threadIdx.x + s];
        __syncthreads();
    }
    if (threadIdx.x == 0)
        out[0] = (float)(sm[0] / (double)((size_t)NB * NB));
}

// ------------------------- launch -------------------------------------------
extern "C" void kernel_launch(void* const* d_in, const int* in_sizes, int n_in,
                              void* d_out, int out_size) {
    const float* F = (const float*)d_in[0];
    const int* labels = (const int*)d_in[1];
    float* out = (float*)d_out;

    uint32_t k1a, k1b, k2a, k2b;
    tf_enc_host(0u, 42u, 0u, 0u, k1a, k1b);
    tf_enc_host(0u, 42u, 0u, 1u, k2a, k2b);

    static int smem_set = 0;
    if (!smem_set) {
        cudaFuncSetAttribute(k_gemm_sample,
                             cudaFuncAttributeMaxDynamicSharedMemorySize,
                             DSM_BYTES);
        smem_set = 1;
    }

    k_split<<<2048, 256>>>(F);
    k_norms<<<NB, 256>>>(F);
    k_gemm_sample<<<784, 256, DSM_BYTES>>>(labels, k1a, k1b, k2a, k2b);
    k_loss<<<NB, 256>>>();
    k_final<<<1, 256>>>(out);
}

// round 11
// speedup vs baseline: 1.2681x; 1.2681x over previous
#include <cuda_runtime.h>
#include <cuda_fp16.h>
#include <cstdint>

#define NB 4096
#define ND 1024
#define F_EPS 1e-6f
#define F_MARGIN 0.3f

// ------------------------- scratch (static device globals; no allocation) ---
__device__ float g_G[(size_t)NB * NB];   // gram matrix F F^T (64 MB)
__device__ float g_t[NB];
__device__ float g_c[NB];
__device__ int   g_pos[NB];
__device__ int   g_neg[NB];
__device__ float g_part[NB];
__device__ __align__(16) uint16_t g_hi[(size_t)NB * ND];  // fp16 hi
__device__ __align__(16) uint16_t g_lo[(size_t)NB * ND];  // fp16 lo

// ------------------------- Threefry-2x32 (20 rounds), JAX-compatible --------
__device__ __forceinline__ uint32_t rotl_d(uint32_t x, int r) {
    return __funnelshift_l(x, x, r);
}
__device__ __forceinline__ void tf_enc(uint32_t k0, uint32_t k1,
                                       uint32_t x0, uint32_t x1,
                                       uint32_t& o0, uint32_t& o1) {
    uint32_t k2 = k0 ^ k1 ^ 0x1BD11BDAu;
    x0 += k0; x1 += k1;
#define TFR(R) { x0 += x1; x1 = rotl_d(x1, R); x1 ^= x0; }
    TFR(13) TFR(15) TFR(26) TFR(6)
    x0 += k1; x1 += k2 + 1u;
    TFR(17) TFR(29) TFR(16) TFR(24)
    x0 += k2; x1 += k0 + 2u;
    TFR(13) TFR(15) TFR(26) TFR(6)
    x0 += k0; x1 += k1 + 3u;
    TFR(17) TFR(29) TFR(16) TFR(24)
    x0 += k1; x1 += k2 + 4u;
    TFR(13) TFR(15) TFR(26) TFR(6)
    x0 += k2; x1 += k0 + 5u;
#undef TFR
    o0 = x0; o1 = x1;
}
static inline uint32_t rotl_h(uint32_t x, int r) { return (x << r) | (x >> (32 - r)); }
static void tf_enc_host(uint32_t k0, uint32_t k1, uint32_t x0, uint32_t x1,
                        uint32_t& o0, uint32_t& o1) {
    uint32_t k2 = k0 ^ k1 ^ 0x1BD11BDAu;
    x0 += k0; x1 += k1;
#define TFRH(R) { x0 += x1; x1 = rotl_h(x1, R); x1 ^= x0; }
    TFRH(13) TFRH(15) TFRH(26) TFRH(6)
    x0 += k1; x1 += k2 + 1u;
    TFRH(17) TFRH(29) TFRH(16) TFRH(24)
    x0 += k2; x1 += k0 + 2u;
    TFRH(13) TFRH(15) TFRH(26) TFRH(6)
    x0 += k0; x1 += k1 + 3u;
    TFRH(17) TFRH(29) TFRH(16) TFRH(24)
    x0 += k1; x1 += k2 + 4u;
    TFRH(13) TFRH(15) TFRH(26) TFRH(6)
    x0 += k2; x1 += k0 + 5u;
#undef TFRH
    o0 = x0; o1 = x1;
}

// ------------------------- sampling kernel ----------------------------------
__global__ void __launch_bounds__(256) k_sample(const int* __restrict__ labels,
                                                uint32_t k1a, uint32_t k1b,
                                                uint32_t k2a, uint32_t k2b) {
    __shared__ int slab[NB];
    __shared__ unsigned long long redn[8], redp[8];
    const int i = blockIdx.x;
    for (int t = threadIdx.x * 4; t < NB; t += 256 * 4)
        *(int4*)&slab[t] = *(const int4*)&labels[t];
    __syncthreads();
    const int Li = slab[i];
    const uint32_t base = (uint32_t)i << 12;

    unsigned long long bestn = 0ull, bestp = 0ull;
    for (int j = threadIdx.x; j < NB; j += 256) {
        uint32_t o0, o1;
        tf_enc(k2a, k2b, 0u, base + (uint32_t)j, o0, o1);
        uint32_t v = ((o0 ^ o1) >> 9) + 1u;
        unsigned long long cand =
            ((unsigned long long)v << 12) | (uint32_t)(4095 - j);
        if (slab[j] != Li) {
            if (cand > bestn) bestn = cand;
        } else {
            uint32_t p0, p1;
            tf_enc(k1a, k1b, 0u, base + (uint32_t)j, p0, p1);
            uint32_t vp = ((p0 ^ p1) >> 9) + 1u;
            unsigned long long candp =
                ((unsigned long long)vp << 12) | (uint32_t)(4095 - j);
            if (candp > bestp) bestp = candp;
        }
    }
    for (int off = 16; off; off >>= 1) {
        unsigned long long a = __shfl_down_sync(0xffffffffu, bestn, off);
        unsigned long long b = __shfl_down_sync(0xffffffffu, bestp, off);
        if (a > bestn) bestn = a;
        if (b > bestp) bestp = b;
    }
    const int warp = threadIdx.x >> 5, lane = threadIdx.x & 31;
    if (lane == 0) { redn[warp] = bestn; redp[warp] = bestp; }
    __syncthreads();
    if (threadIdx.x == 0) {
        unsigned long long bn = 0ull, bp = 0ull;
        for (int w = 0; w < 8; w++) {
            if (redn[w] > bn) bn = redn[w];
            if (redp[w] > bp) bp = redp[w];
        }
        g_neg[i] = 4095 - (int)(bn & 0xFFFu);
        g_pos[i] = 4095 - (int)(bp & 0xFFFu);
    }
}

// ------------------------- fused fp16 split + row norms ---------------------
__global__ void __launch_bounds__(256) k_prep(const float* __restrict__ F) {
    const int i = blockIdx.x, tid = threadIdx.x;
    const float4 v = *(const float4*)(F + (size_t)i * ND + tid * 4);
    float x[4] = {v.x, v.y, v.z, v.w};
    uint16_t h[4], l[4];
    float n2 = 0.f, s = 0.f;
#pragma unroll
    for (int e = 0; e < 4; e++) {
        __half hb = __float2half_rn(x[e]);
        __half lb = __float2half_rn(x[e] - __half2float(hb));
        h[e] = *(uint16_t*)&hb;
        l[e] = *(uint16_t*)&lb;
        n2 = fmaf(x[e], x[e], n2);
        s += x[e];
    }
    *(uint64_t*)(g_hi + (size_t)i * ND + tid * 4) = *(const uint64_t*)h;
    *(uint64_t*)(g_lo + (size_t)i * ND + tid * 4) = *(const uint64_t*)l;

    for (int off = 16; off; off >>= 1) {
        n2 += __shfl_down_sync(0xffffffffu, n2, off);
        s  += __shfl_down_sync(0xffffffffu, s,  off);
    }
    __shared__ float sn[8], ss[8];
    const int warp = tid >> 5, lane = tid & 31;
    if (lane == 0) { sn[warp] = n2; ss[warp] = s; }
    __syncthreads();
    if (tid == 0) {
        float a = 0.f, b = 0.f;
        for (int w = 0; w < 8; w++) { a += sn[w]; b += ss[w]; }
        g_t[i] = a + 2.f * F_EPS * b + (float)ND * F_EPS * F_EPS;
        g_c[i] = a - 2.f * F_EPS * b;
    }
}

// ------------------------- mma.sync GEMM helpers ----------------------------
__device__ __forceinline__ uint32_t smem_u32(const void* p) {
    uint32_t a;
    asm("{ .reg .u64 t; cvta.to.shared.u64 t, %1; cvt.u32.u64 %0, t; }"
        : "=r"(a) : "l"(p));
    return a;
}
#define LDSM4(r0, r1, r2, r3, addr)                                          \
    asm volatile("ldmatrix.sync.aligned.m8n8.x4.shared.b16 {%0,%1,%2,%3}, [%4];" \
                 : "=r"(r0), "=r"(r1), "=r"(r2), "=r"(r3) : "r"(addr))
#define MMA16816(c, a0, a1, a2, a3, b0, b1)                                  \
    asm volatile("mma.sync.aligned.m16n8k16.row.col.f32.f16.f16.f32 "        \
                 "{%0,%1,%2,%3}, {%4,%5,%6,%7}, {%8,%9}, {%0,%1,%2,%3};"     \
                 : "+f"((c)[0]), "+f"((c)[1]), "+f"((c)[2]), "+f"((c)[3])    \
                 : "r"(a0), "r"(a1), "r"(a2), "r"(a3), "r"(b0), "r"(b1))
#define CP16(saddr, gptr)                                                    \
    asm volatile("cp.async.cg.shared.global [%0], [%1], 16;"                 \
                 :: "r"(saddr), "l"(gptr) : "memory")

// smem stage: 3 tiles of 8192 B (Ahi, Bhi, Blo), 3 stages.
// Each tile: 128 rows x 64 B (32 fp16), 16B chunks swizzled c' = c ^ ((m>>1)&3).
#define STAGE_BYTES 24576
#define TILE_BYTES  8192
#define DSM_BYTES   73728   // 3 stages; also covers 128x132 transpose (67584)

// --------------- tensor-core GEMM: G = Hi * (Hi + Lo)^T (2 products) --------
__global__ void __launch_bounds__(256, 2) k_gemm_mma() {
    // triangle decode: bid -> (bx, by), by <= bx
    int bid = blockIdx.x;
    int bx = (int)((sqrt(8.0 * (double)bid + 1.0) - 1.0) * 0.5);
    while ((bx + 1) * (bx + 2) / 2 <= bid) bx++;
    while (bx * (bx + 1) / 2 > bid) bx--;
    int by = bid - bx * (bx + 1) / 2;

    extern __shared__ char dsm[];
    const uint32_t smemBase = smem_u32(dsm);
    const int tid = threadIdx.x;
    const int lane = tid & 31, wid = tid >> 5;
    const int wm = wid >> 2, wn = wid & 3;   // warp tile: 64(m) x 32(n)

    const uint16_t* gsrc[3];
    gsrc[0] = g_hi + (size_t)(bx * 128) * ND;   // A hi
    gsrc[1] = g_hi + (size_t)(by * 128) * ND;   // B hi
    gsrc[2] = g_lo + (size_t)(by * 128) * ND;   // B lo

    float acc[4][4][4];
#pragma unroll
    for (int a = 0; a < 4; a++)
#pragma unroll
        for (int b = 0; b < 4; b++)
#pragma unroll
            for (int c = 0; c < 4; c++) acc[a][b][c] = 0.f;

#define LOAD_STAGE(S, KT)                                                     \
    {                                                                         \
        _Pragma("unroll")                                                     \
        for (int i = 0; i < 6; i++) {                                         \
            int idx = tid + i * 256;                                          \
            int tile = idx >> 9;                                              \
            int m = (idx >> 2) & 127;                                         \
            int c = idx & 3;                                                  \
            const uint16_t* gp = gsrc[tile] + (size_t)m * ND + (KT) + c * 8;  \
            uint32_t sa = smemBase + (uint32_t)(S) * STAGE_BYTES +            \
                          tile * TILE_BYTES + m * 64 +                        \
                          ((c ^ ((m >> 1) & 3)) * 16);                        \
            CP16(sa, gp);                                                     \
        }                                                                     \
    }

    LOAD_STAGE(0, 0)
    asm volatile("cp.async.commit_group;" ::: "memory");
    LOAD_STAGE(1, 32)
    asm volatile("cp.async.commit_group;" ::: "memory");

    const int r15 = lane & 15, kh = lane >> 4;
    const uint32_t rA = (uint32_t)(wm * 64 + r15);
    const uint32_t rB = (uint32_t)(wn * 32 + r15);
    const uint32_t swA = (rA >> 1) & 3, swB = (rB >> 1) & 3;

    int stC = 0, stP = 2;
#pragma unroll 1
    for (int kc = 0; kc < 32; kc++) {
        asm volatile("cp.async.wait_group 1;" ::: "memory");
        __syncthreads();
        if (kc + 2 < 32) LOAD_STAGE(stP, (kc + 2) * 32)
        asm volatile("cp.async.commit_group;" ::: "memory");

        const uint32_t sb = smemBase + (uint32_t)stC * STAGE_BYTES;
        const uint32_t aH = sb;
        const uint32_t bH = sb + TILE_BYTES, bL = sb + 2 * TILE_BYTES;

#pragma unroll
        for (int k16 = 0; k16 < 2; k16++) {
            const uint32_t cIdx = (uint32_t)(k16 * 2 + kh);
            const uint32_t cpA = (cIdx ^ swA) * 16u;
            const uint32_t cpB = (cIdx ^ swB) * 16u;
            // --- B fragments (4 LDSM: hi + lo) ---
            uint32_t bh[4][2], bl[4][2];
            {
                uint32_t r0, r1, r2, r3;
                LDSM4(r0, r1, r2, r3, bH + rB * 64 + cpB);
                bh[0][0] = r0; bh[1][0] = r1; bh[0][1] = r2; bh[1][1] = r3;
                LDSM4(r0, r1, r2, r3, bH + (rB + 16) * 64 + cpB);
                bh[2][0] = r0; bh[3][0] = r1; bh[2][1] = r2; bh[3][1] = r3;
                LDSM4(r0, r1, r2, r3, bL + rB * 64 + cpB);
                bl[0][0] = r0; bl[1][0] = r1; bl[0][1] = r2; bl[1][1] = r3;
                LDSM4(r0, r1, r2, r3, bL + (rB + 16) * 64 + cpB);
                bl[2][0] = r0; bl[3][0] = r1; bl[2][1] = r2; bl[3][1] = r3;
            }
#pragma unroll
            for (int mt = 0; mt < 4; mt++) {
                uint32_t a0, a1, a2, a3;
                LDSM4(a0, a1, a2, a3,
                      aH + (rA + (uint32_t)mt * 16) * 64 + cpA);
#pragma unroll
                for (int nt = 0; nt < 4; nt++)
                    MMA16816(acc[mt][nt], a0, a1, a2, a3, bh[nt][0], bh[nt][1]);
#pragma unroll
                for (int nt = 0; nt < 4; nt++)
                    MMA16816(acc[mt][nt], a0, a1, a2, a3, bl[nt][0], bl[nt][1]);
            }
        }
        stC = (stC == 2) ? 0 : stC + 1;
        stP = (stP == 2) ? 0 : stP + 1;
    }

    // ---------------- epilogue: direct tile + mirror via smem transpose -----
    const int r0 = bx * 128, c0 = by * 128;
    const int qr = lane >> 2, qc = 2 * (lane & 3);
#pragma unroll
    for (int mt = 0; mt < 4; mt++)
#pragma unroll
        for (int nt = 0; nt < 4; nt++) {
            int row = r0 + wm * 64 + mt * 16 + qr;
            int col = c0 + wn * 32 + nt * 8 + qc;
            float2 v01 = make_float2(acc[mt][nt][0], acc[mt][nt][1]);
            float2 v23 = make_float2(acc[mt][nt][2], acc[mt][nt][3]);
            *(float2*)&g_G[(size_t)row * NB + col] = v01;
            *(float2*)&g_G[(size_t)(row + 8) * NB + col] = v23;
        }

    if (bx != by) {
        float (*sT)[132] = (float (*)[132])dsm;   // [n][m], 128x132 floats
        __syncthreads();   // compute buffers dead; reuse smem
#pragma unroll
        for (int mt = 0; mt < 4; mt++)
#pragma unroll
            for (int nt = 0; nt < 4; nt++) {
                int rl = wm * 64 + mt * 16 + qr;
                int cl = wn * 32 + nt * 8 + qc;
                sT[cl][rl]         = acc[mt][nt][0];
                sT[cl + 1][rl]     = acc[mt][nt][1];
                sT[cl][rl + 8]     = acc[mt][nt][2];
                sT[cl + 1][rl + 8] = acc[mt][nt][3];
            }
        __syncthreads();
#pragma unroll
        for (int e = tid * 4; e < 128 * 128; e += 256 * 4) {
            int n = e >> 7, m = e & 127;
            float4 v = *(float4*)&sT[n][m];
            *(float4*)&g_G[(size_t)(c0 + n) * NB + r0 + m] = v;
        }
    }
#undef LOAD_STAGE
}

// ------------------------- loss reduction -----------------------------------
__device__ __forceinline__ float pairterm(float t, float gp, float gq,
                                          float cp, float cq) {
    float sap = fmaxf(fmaf(-2.f, gp, t + cp), 1e-12f);
    float san = fmaxf(fmaf(-2.f, gq, t + cq), 1e-12f);
    float dap, dan;
    asm("sqrt.approx.f32 %0, %1;" : "=f"(dap) : "f"(sap));
    asm("sqrt.approx.f32 %0, %1;" : "=f"(dan) : "f"(san));
    return fmaxf(dap - dan + F_MARGIN, 0.f);
}

__global__ void __launch_bounds__(256) k_loss() {
    const int i = blockIdx.x;
    const int p = g_pos[i], q = g_neg[i];
    const float cp = g_c[p], cq = g_c[q];
    const float4* Gp = (const float4*)(g_G + (size_t)p * NB);
    const float4* Gq = (const float4*)(g_G + (size_t)q * NB);
    const float4* T  = (const float4*)g_t;
    float acc = 0.f;
    for (int j = threadIdx.x; j < NB / 4; j += 256) {
        float4 gp = Gp[j], gq = Gq[j], tt = T[j];
        acc += pairterm(tt.x, gp.x, gq.x, cp, cq);
        acc += pairterm(tt.y, gp.y, gq.y, cp, cq);
        acc += pairterm(tt.z, gp.z, gq.z, cp, cq);
        acc += pairterm(tt.w, gp.w, gq.w, cp, cq);
    }
    for (int off = 16; off; off >>= 1)
        acc += __shfl_down_sync(0xffffffffu, acc, off);
    __shared__ float sa[8];
    const int warp = threadIdx.x >> 5, lane = threadIdx.x & 31;
    if (lane == 0) sa[warp] = acc;
    __syncthreads();
    if (threadIdx.x == 0) {
        float s = 0.f;
        for (int w = 0; w < 8; w++) s += sa[w];
        g_part[i] = s;
    }
}

__global__ void __launch_bounds__(256) k_final(float* __restrict__ out) {
    __shared__ double sm[256];
    double a = 0.0;
    for (int i = threadIdx.x; i < NB; i += 256) a += (double)g_part[i];
    sm[threadIdx.x] = a;
    __syncthreads();
    for (int s = 128; s; s >>= 1) {
        if (threadIdx.x < s) sm[threadIdx.x] += sm[threadIdx.x + s];
        __syncthreads();
    }
    if (threadIdx.x == 0)
        out[0] = (float)(sm[0] / (double)((size_t)NB * NB));
}

// ------------------------- launch -------------------------------------------
extern "C" void kernel_launch(void* const* d_in, const int* in_sizes, int n_in,
                              void* d_out, int out_size) {
    const float* F = (const float*)d_in[0];
    const int* labels = (const int*)d_in[1];
    float* out = (float*)d_out;

    uint32_t k1a, k1b, k2a, k2b;
    tf_enc_host(0u, 42u, 0u, 0u, k1a, k1b);
    tf_enc_host(0u, 42u, 0u, 1u, k2a, k2b);

    static int smem_set = 0;
    if (!smem_set) {
        cudaFuncSetAttribute(k_gemm_mma,
                             cudaFuncAttributeMaxDynamicSharedMemorySize,
                             DSM_BYTES);
        smem_set = 1;
    }

    k_prep<<<NB, 256>>>(F);
    k_sample<<<NB, 256>>>(labels, k1a, k1b, k2a, k2b);
    k_gemm_mma<<<528, 256, DSM_BYTES>>>();
    k_loss<<<NB, 256>>>();
    k_final<<<1, 256>>>(out);
}

// round 14
// speedup vs baseline: 1.2876x; 1.0154x over previous
#include <cuda_runtime.h>
#include <cuda_fp16.h>
#include <cstdint>

#define NB 4096
#define ND 1024
#define F_EPS 1e-6f
#define F_MARGIN 0.3f

// ------------------------- scratch (static device globals; no allocation) ---
__device__ float g_G[(size_t)NB * NB];   // gram matrix F F^T (64 MB)
__device__ float g_t[NB];
__device__ float g_c[NB];
__device__ int   g_pos[NB];
__device__ int   g_neg[NB];
__device__ float g_part[NB];
__device__ __align__(16) uint16_t g_hi[(size_t)NB * ND];  // fp16 hi
__device__ __align__(16) uint16_t g_lo[(size_t)NB * ND];  // fp16 lo

// ------------------------- Threefry-2x32 (20 rounds), JAX-compatible --------
__device__ __forceinline__ uint32_t rotl_d(uint32_t x, int r) {
    return __funnelshift_l(x, x, r);
}
__device__ __forceinline__ void tf_enc(uint32_t k0, uint32_t k1,
                                       uint32_t x0, uint32_t x1,
                                       uint32_t& o0, uint32_t& o1) {
    uint32_t k2 = k0 ^ k1 ^ 0x1BD11BDAu;
    x0 += k0; x1 += k1;
#define TFR(R) { x0 += x1; x1 = rotl_d(x1, R); x1 ^= x0; }
    TFR(13) TFR(15) TFR(26) TFR(6)
    x0 += k1; x1 += k2 + 1u;
    TFR(17) TFR(29) TFR(16) TFR(24)
    x0 += k2; x1 += k0 + 2u;
    TFR(13) TFR(15) TFR(26) TFR(6)
    x0 += k0; x1 += k1 + 3u;
    TFR(17) TFR(29) TFR(16) TFR(24)
    x0 += k1; x1 += k2 + 4u;
    TFR(13) TFR(15) TFR(26) TFR(6)
    x0 += k2; x1 += k0 + 5u;
#undef TFR
    o0 = x0; o1 = x1;
}
static inline uint32_t rotl_h(uint32_t x, int r) { return (x << r) | (x >> (32 - r)); }
static void tf_enc_host(uint32_t k0, uint32_t k1, uint32_t x0, uint32_t x1,
                        uint32_t& o0, uint32_t& o1) {
    uint32_t k2 = k0 ^ k1 ^ 0x1BD11BDAu;
    x0 += k0; x1 += k1;
#define TFRH(R) { x0 += x1; x1 = rotl_h(x1, R); x1 ^= x0; }
    TFRH(13) TFRH(15) TFRH(26) TFRH(6)
    x0 += k1; x1 += k2 + 1u;
    TFRH(17) TFRH(29) TFRH(16) TFRH(24)
    x0 += k2; x1 += k0 + 2u;
    TFRH(13) TFRH(15) TFRH(26) TFRH(6)
    x0 += k0; x1 += k1 + 3u;
    TFRH(17) TFRH(29) TFRH(16) TFRH(24)
    x0 += k1; x1 += k2 + 4u;
    TFRH(13) TFRH(15) TFRH(26) TFRH(6)
    x0 += k2; x1 += k0 + 5u;
#undef TFRH
    o0 = x0; o1 = x1;
}

// ------------------------- sampling kernel ----------------------------------
__global__ void __launch_bounds__(256) k_sample(const int* __restrict__ labels,
                                                uint32_t k1a, uint32_t k1b,
                                                uint32_t k2a, uint32_t k2b) {
    __shared__ int slab[NB];
    __shared__ unsigned long long redn[8], redp[8];
    const int i = blockIdx.x;
    for (int t = threadIdx.x * 4; t < NB; t += 256 * 4)
        *(int4*)&slab[t] = *(const int4*)&labels[t];
    __syncthreads();
    const int Li = slab[i];
    const uint32_t base = (uint32_t)i << 12;

    unsigned long long bestn = 0ull, bestp = 0ull;
    for (int j = threadIdx.x; j < NB; j += 256) {
        uint32_t o0, o1;
        tf_enc(k2a, k2b, 0u, base + (uint32_t)j, o0, o1);
        uint32_t v = ((o0 ^ o1) >> 9) + 1u;
        unsigned long long cand =
            ((unsigned long long)v << 12) | (uint32_t)(4095 - j);
        if (slab[j] != Li) {
            if (cand > bestn) bestn = cand;
        } else {
            uint32_t p0, p1;
            tf_enc(k1a, k1b, 0u, base + (uint32_t)j, p0, p1);
            uint32_t vp = ((p0 ^ p1) >> 9) + 1u;
            unsigned long long candp =
                ((unsigned long long)vp << 12) | (uint32_t)(4095 - j);
            if (candp > bestp) bestp = candp;
        }
    }
    for (int off = 16; off; off >>= 1) {
        unsigned long long a = __shfl_down_sync(0xffffffffu, bestn, off);
        unsigned long long b = __shfl_down_sync(0xffffffffu, bestp, off);
        if (a > bestn) bestn = a;
        if (b > bestp) bestp = b;
    }
    const int warp = threadIdx.x >> 5, lane = threadIdx.x & 31;
    if (lane == 0) { redn[warp] = bestn; redp[warp] = bestp; }
    __syncthreads();
    if (threadIdx.x == 0) {
        unsigned long long bn = 0ull, bp = 0ull;
        for (int w = 0; w < 8; w++) {
            if (redn[w] > bn) bn = redn[w];
            if (redp[w] > bp) bp = redp[w];
        }
        g_neg[i] = 4095 - (int)(bn & 0xFFFu);
        g_pos[i] = 4095 - (int)(bp & 0xFFFu);
    }
}

// ------------------------- fused fp16 split + row norms ---------------------
__global__ void __launch_bounds__(256) k_prep(const float* __restrict__ F) {
    const int i = blockIdx.x, tid = threadIdx.x;
    const float4 v = *(const float4*)(F + (size_t)i * ND + tid * 4);
    float x[4] = {v.x, v.y, v.z, v.w};
    uint16_t h[4], l[4];
    float n2 = 0.f, s = 0.f;
#pragma unroll
    for (int e = 0; e < 4; e++) {
        __half hb = __float2half_rn(x[e]);
        __half lb = __float2half_rn(x[e] - __half2float(hb));
        h[e] = *(uint16_t*)&hb;
        l[e] = *(uint16_t*)&lb;
        n2 = fmaf(x[e], x[e], n2);
        s += x[e];
    }
    *(uint64_t*)(g_hi + (size_t)i * ND + tid * 4) = *(const uint64_t*)h;
    *(uint64_t*)(g_lo + (size_t)i * ND + tid * 4) = *(const uint64_t*)l;

    for (int off = 16; off; off >>= 1) {
        n2 += __shfl_down_sync(0xffffffffu, n2, off);
        s  += __shfl_down_sync(0xffffffffu, s,  off);
    }
    __shared__ float sn[8], ss[8];
    const int warp = tid >> 5, lane = tid & 31;
    if (lane == 0) { sn[warp] = n2; ss[warp] = s; }
    __syncthreads();
    if (tid == 0) {
        float a = 0.f, b = 0.f;
        for (int w = 0; w < 8; w++) { a += sn[w]; b += ss[w]; }
        g_t[i] = a + 2.f * F_EPS * b + (float)ND * F_EPS * F_EPS;
        g_c[i] = a - 2.f * F_EPS * b;
    }
}

// ------------------------- mma.sync GEMM helpers ----------------------------
__device__ __forceinline__ uint32_t smem_u32(const void* p) {
    uint32_t a;
    asm("{ .reg .u64 t; cvta.to.shared.u64 t, %1; cvt.u32.u64 %0, t; }"
        : "=r"(a) : "l"(p));
    return a;
}
#define LDSM4(r0, r1, r2, r3, addr)                                          \
    asm volatile("ldmatrix.sync.aligned.m8n8.x4.shared.b16 {%0,%1,%2,%3}, [%4];" \
                 : "=r"(r0), "=r"(r1), "=r"(r2), "=r"(r3) : "r"(addr))
#define MMA16816(c, a0, a1, a2, a3, b0, b1)                                  \
    asm volatile("mma.sync.aligned.m16n8k16.row.col.f32.f16.f16.f32 "        \
                 "{%0,%1,%2,%3}, {%4,%5,%6,%7}, {%8,%9}, {%0,%1,%2,%3};"     \
                 : "+f"((c)[0]), "+f"((c)[1]), "+f"((c)[2]), "+f"((c)[3])    \
                 : "r"(a0), "r"(a1), "r"(a2), "r"(a3), "r"(b0), "r"(b1))
#define CP16(saddr, gptr)                                                    \
    asm volatile("cp.async.cg.shared.global [%0], [%1], 16;"                 \
                 :: "r"(saddr), "l"(gptr) : "memory")

// smem stage: 3 tiles of 8192 B (Ahi, Bhi, Blo), 3 stages.
// Each tile: 128 rows x 64 B (32 fp16), 16B chunks swizzled c' = c ^ ((m>>1)&3).
#define STAGE_BYTES 24576
#define TILE_BYTES  8192
#define DSM_BYTES   73728   // 3 stages; also covers 128x132 transpose (67584)

// --------------- tensor-core GEMM: G = Hi * (Hi + Lo)^T (2 products) --------
__global__ void __launch_bounds__(256, 2) k_gemm_mma() {
    // triangle decode: bid -> (bx, by), by <= bx
    int bid = blockIdx.x;
    int bx = (int)((sqrt(8.0 * (double)bid + 1.0) - 1.0) * 0.5);
    while ((bx + 1) * (bx + 2) / 2 <= bid) bx++;
    while (bx * (bx + 1) / 2 > bid) bx--;
    int by = bid - bx * (bx + 1) / 2;

    extern __shared__ char dsm[];
    const uint32_t smemBase = smem_u32(dsm);
    const int tid = threadIdx.x;
    const int lane = tid & 31, wid = tid >> 5;
    const int wm = wid >> 2, wn = wid & 3;   // warp tile: 64(m) x 32(n)

    const uint16_t* gsrc[3];
    gsrc[0] = g_hi + (size_t)(bx * 128) * ND;   // A hi
    gsrc[1] = g_hi + (size_t)(by * 128) * ND;   // B hi
    gsrc[2] = g_lo + (size_t)(by * 128) * ND;   // B lo

    float acc[4][4][4];
#pragma unroll
    for (int a = 0; a < 4; a++)
#pragma unroll
        for (int b = 0; b < 4; b++)
#pragma unroll
            for (int c = 0; c < 4; c++) acc[a][b][c] = 0.f;

#define LOAD_STAGE(S, KT)                                                     \
    {                                                                         \
        _Pragma("unroll")                                                     \
        for (int i = 0; i < 6; i++) {                                         \
            int idx = tid + i * 256;                                          \
            int tile = idx >> 9;                                              \
            int m = (idx >> 2) & 127;                                         \
            int c = idx & 3;                                                  \
            const uint16_t* gp = gsrc[tile] + (size_t)m * ND + (KT) + c * 8;  \
            uint32_t sa = smemBase + (uint32_t)(S) * STAGE_BYTES +            \
                          tile * TILE_BYTES + m * 64 +                        \
                          ((c ^ ((m >> 1) & 3)) * 16);                        \
            CP16(sa, gp);                                                     \
        }                                                                     \
    }

    LOAD_STAGE(0, 0)
    asm volatile("cp.async.commit_group;" ::: "memory");
    LOAD_STAGE(1, 32)
    asm volatile("cp.async.commit_group;" ::: "memory");

    const int r15 = lane & 15, kh = lane >> 4;
    const uint32_t rA = (uint32_t)(wm * 64 + r15);
    const uint32_t rB = (uint32_t)(wn * 32 + r15);
    const uint32_t swA = (rA >> 1) & 3, swB = (rB >> 1) & 3;

    int stC = 0, stP = 2;
#pragma unroll 1
    for (int kc = 0; kc < 32; kc++) {
        asm volatile("cp.async.wait_group 1;" ::: "memory");
        __syncthreads();
        if (kc + 2 < 32) LOAD_STAGE(stP, (kc + 2) * 32)
        asm volatile("cp.async.commit_group;" ::: "memory");

        const uint32_t sb = smemBase + (uint32_t)stC * STAGE_BYTES;
        const uint32_t aH = sb;
        const uint32_t bH = sb + TILE_BYTES, bL = sb + 2 * TILE_BYTES;

#pragma unroll
        for (int k16 = 0; k16 < 2; k16++) {
            const uint32_t cIdx = (uint32_t)(k16 * 2 + kh);
            const uint32_t cpA = (cIdx ^ swA) * 16u;
            const uint32_t cpB = (cIdx ^ swB) * 16u;
            // --- B fragments (4 LDSM: hi + lo) ---
            uint32_t bh[4][2], bl[4][2];
            {
                uint32_t r0, r1, r2, r3;
                LDSM4(r0, r1, r2, r3, bH + rB * 64 + cpB);
                bh[0][0] = r0; bh[1][0] = r1; bh[0][1] = r2; bh[1][1] = r3;
                LDSM4(r0, r1, r2, r3, bH + (rB + 16) * 64 + cpB);
                bh[2][0] = r0; bh[3][0] = r1; bh[2][1] = r2; bh[3][1] = r3;
                LDSM4(r0, r1, r2, r3, bL + rB * 64 + cpB);
                bl[0][0] = r0; bl[1][0] = r1; bl[0][1] = r2; bl[1][1] = r3;
                LDSM4(r0, r1, r2, r3, bL + (rB + 16) * 64 + cpB);
                bl[2][0] = r0; bl[3][0] = r1; bl[2][1] = r2; bl[3][1] = r3;
            }
#pragma unroll
            for (int mt = 0; mt < 4; mt++) {
                uint32_t a0, a1, a2, a3;
                LDSM4(a0, a1, a2, a3,
                      aH + (rA + (uint32_t)mt * 16) * 64 + cpA);
#pragma unroll
                for (int nt = 0; nt < 4; nt++)
                    MMA16816(acc[mt][nt], a0, a1, a2, a3, bh[nt][0], bh[nt][1]);
#pragma unroll
                for (int nt = 0; nt < 4; nt++)
                    MMA16816(acc[mt][nt], a0, a1, a2, a3, bl[nt][0], bl[nt][1]);
            }
        }
        stC = (stC == 2) ? 0 : stC + 1;
        stP = (stP == 2) ? 0 : stP + 1;
    }

    // ---------------- epilogue: direct tile + mirror via smem transpose -----
    const int r0 = bx * 128, c0 = by * 128;
    const int qr = lane >> 2, qc = 2 * (lane & 3);
#pragma unroll
    for (int mt = 0; mt < 4; mt++)
#pragma unroll
        for (int nt = 0; nt < 4; nt++) {
            int row = r0 + wm * 64 + mt * 16 + qr;
            int col = c0 + wn * 32 + nt * 8 + qc;
            float2 v01 = make_float2(acc[mt][nt][0], acc[mt][nt][1]);
            float2 v23 = make_float2(acc[mt][nt][2], acc[mt][nt][3]);
            *(float2*)&g_G[(size_t)row * NB + col] = v01;
            *(float2*)&g_G[(size_t)(row + 8) * NB + col] = v23;
        }

    if (bx != by) {
        float (*sT)[132] = (float (*)[132])dsm;   // [n][m], 128x132 floats
        __syncthreads();   // compute buffers dead; reuse smem
#pragma unroll
        for (int mt = 0; mt < 4; mt++)
#pragma unroll
            for (int nt = 0; nt < 4; nt++) {
                int rl = wm * 64 + mt * 16 + qr;
                int cl = wn * 32 + nt * 8 + qc;
                sT[cl][rl]         = acc[mt][nt][0];
                sT[cl + 1][rl]     = acc[mt][nt][1];
                sT[cl][rl + 8]     = acc[mt][nt][2];
                sT[cl + 1][rl + 8] = acc[mt][nt][3];
            }
        __syncthreads();
#pragma unroll
        for (int e = tid * 4; e < 128 * 128; e += 256 * 4) {
            int n = e >> 7, m = e & 127;
            float4 v = *(float4*)&sT[n][m];
            *(float4*)&g_G[(size_t)(c0 + n) * NB + r0 + m] = v;
        }
    }
#undef LOAD_STAGE
}

// ------------------------- loss reduction -----------------------------------
__device__ __forceinline__ float pairterm(float t, float gp, float gq,
                                          float cp, float cq) {
    float sap = fmaxf(fmaf(-2.f, gp, t + cp), 1e-12f);
    float san = fmaxf(fmaf(-2.f, gq, t + cq), 1e-12f);
    float dap, dan;
    asm("sqrt.approx.f32 %0, %1;" : "=f"(dap) : "f"(sap));
    asm("sqrt.approx.f32 %0, %1;" : "=f"(dan) : "f"(san));
    return fmaxf(dap - dan + F_MARGIN, 0.f);
}

__global__ void __launch_bounds__(256) k_loss() {
    const int i = blockIdx.x;
    const int p = g_pos[i], q = g_neg[i];
    const float cp = g_c[p], cq = g_c[q];
    const float4* Gp = (const float4*)(g_G + (size_t)p * NB);
    const float4* Gq = (const float4*)(g_G + (size_t)q * NB);
    const float4* T  = (const float4*)g_t;
    float acc = 0.f;
    for (int j = threadIdx.x; j < NB / 4; j += 256) {
        float4 gp = Gp[j], gq = Gq[j], tt = T[j];
        acc += pairterm(tt.x, gp.x, gq.x, cp, cq);
        acc += pairterm(tt.y, gp.y, gq.y, cp, cq);
        acc += pairterm(tt.z, gp.z, gq.z, cp, cq);
        acc += pairterm(tt.w, gp.w, gq.w, cp, cq);
    }
    for (int off = 16; off; off >>= 1)
        acc += __shfl_down_sync(0xffffffffu, acc, off);
    __shared__ float sa[8];
    const int warp = threadIdx.x >> 5, lane = threadIdx.x & 31;
    if (lane == 0) sa[warp] = acc;
    __syncthreads();
    if (threadIdx.x == 0) {
        float s = 0.f;
        for (int w = 0; w < 8; w++) s += sa[w];
        g_part[i] = s;
    }
}

__global__ void __launch_bounds__(256) k_final(float* __restrict__ out) {
    __shared__ double sm[256];
    double a = 0.0;
    for (int i = threadIdx.x; i < NB; i += 256) a += (double)g_part[i];
    sm[threadIdx.x] = a;
    __syncthreads();
    for (int s = 128; s; s >>= 1) {
        if (threadIdx.x < s) sm[threadIdx.x] += sm[threadIdx.x + s];
        __syncthreads();
    }
    if (threadIdx.x == 0)
        out[0] = (float)(sm[0] / (double)((size_t)NB * NB));
}

// ------------------------- launch -------------------------------------------
extern "C" void kernel_launch(void* const* d_in, const int* in_sizes, int n_in,
                              void* d_out, int out_size) {
    const float* F = (const float*)d_in[0];
    const int* labels = (const int*)d_in[1];
    float* out = (float*)d_out;

    uint32_t k1a, k1b, k2a, k2b;
    tf_enc_host(0u, 42u, 0u, 0u, k1a, k1b);
    tf_enc_host(0u, 42u, 0u, 1u, k2a, k2b);

    static bool init_done = false;
    static bool have_side = false;
    static cudaStream_t s_side;
    static cudaEvent_t ev_fork, ev_join;
    if (!init_done) {
        cudaFuncSetAttribute(k_gemm_mma,
                             cudaFuncAttributeMaxDynamicSharedMemorySize,
                             DSM_BYTES);
        have_side =
            (cudaStreamCreateWithFlags(&s_side, cudaStreamNonBlocking) ==
             cudaSuccess) &&
            (cudaEventCreateWithFlags(&ev_fork, cudaEventDisableTiming) ==
             cudaSuccess) &&
            (cudaEventCreateWithFlags(&ev_join, cudaEventDisableTiming) ==
             cudaSuccess);
        init_done = true;
    }

    if (have_side) {
        // fork: sampling (pure ALU) overlaps prep + tensor GEMM
        cudaEventRecord(ev_fork, 0);
        cudaStreamWaitEvent(s_side, ev_fork, 0);
        k_sample<<<NB, 256, 0, s_side>>>(labels, k1a, k1b, k2a, k2b);
        cudaEventRecord(ev_join, s_side);

        k_prep<<<NB, 256>>>(F);
        k_gemm_mma<<<528, 256, DSM_BYTES>>>();

        cudaStreamWaitEvent(0, ev_join, 0);   // join before loss
    } else {
        k_sample<<<NB, 256>>>(labels, k1a, k1b, k2a, k2b);
        k_prep<<<NB, 256>>>(F);
        k_gemm_mma<<<528, 256, DSM_BYTES>>>();
    }
    k_loss<<<NB, 256>>>();
    k_final<<<1, 256>>>(out);
}

// round 15
// speedup vs baseline: 1.6486x; 1.2804x over previous
#include <cuda_runtime.h>
#include <cuda_fp16.h>
#include <cstdint>

#define NB 4096
#define ND 1024
#define F_EPS 1e-6f
#define F_MARGIN 0.3f

// ------------------------- scratch (static device globals; no allocation) ---
__device__ float g_G[(size_t)NB * NB];   // gram matrix F F^T (64 MB)
__device__ float g_t[NB];
__device__ float g_c[NB];
__device__ int   g_pos[NB];
__device__ int   g_neg[NB];
__device__ float g_part[NB];
__device__ __align__(16) uint16_t g_hi[(size_t)NB * ND];  // fp16 hi

// ------------------------- Threefry-2x32 (20 rounds), JAX-compatible --------
__device__ __forceinline__ uint32_t rotl_d(uint32_t x, int r) {
    return __funnelshift_l(x, x, r);
}
__device__ __forceinline__ void tf_enc(uint32_t k0, uint32_t k1,
                                       uint32_t x0, uint32_t x1,
                                       uint32_t& o0, uint32_t& o1) {
    uint32_t k2 = k0 ^ k1 ^ 0x1BD11BDAu;
    x0 += k0; x1 += k1;
#define TFR(R) { x0 += x1; x1 = rotl_d(x1, R); x1 ^= x0; }
    TFR(13) TFR(15) TFR(26) TFR(6)
    x0 += k1; x1 += k2 + 1u;
    TFR(17) TFR(29) TFR(16) TFR(24)
    x0 += k2; x1 += k0 + 2u;
    TFR(13) TFR(15) TFR(26) TFR(6)
    x0 += k0; x1 += k1 + 3u;
    TFR(17) TFR(29) TFR(16) TFR(24)
    x0 += k1; x1 += k2 + 4u;
    TFR(13) TFR(15) TFR(26) TFR(6)
    x0 += k2; x1 += k0 + 5u;
#undef TFR
    o0 = x0; o1 = x1;
}
static inline uint32_t rotl_h(uint32_t x, int r) { return (x << r) | (x >> (32 - r)); }
static void tf_enc_host(uint32_t k0, uint32_t k1, uint32_t x0, uint32_t x1,
                        uint32_t& o0, uint32_t& o1) {
    uint32_t k2 = k0 ^ k1 ^ 0x1BD11BDAu;
    x0 += k0; x1 += k1;
#define TFRH(R) { x0 += x1; x1 = rotl_h(x1, R); x1 ^= x0; }
    TFRH(13) TFRH(15) TFRH(26) TFRH(6)
    x0 += k1; x1 += k2 + 1u;
    TFRH(17) TFRH(29) TFRH(16) TFRH(24)
    x0 += k2; x1 += k0 + 2u;
    TFRH(13) TFRH(15) TFRH(26) TFRH(6)
    x0 += k0; x1 += k1 + 3u;
    TFRH(17) TFRH(29) TFRH(16) TFRH(24)
    x0 += k1; x1 += k2 + 4u;
    TFRH(13) TFRH(15) TFRH(26) TFRH(6)
    x0 += k2; x1 += k0 + 5u;
#undef TFRH
    o0 = x0; o1 = x1;
}

// ------------------------- sampling kernel ----------------------------------
__global__ void __launch_bounds__(256) k_sample(const int* __restrict__ labels,
                                                uint32_t k1a, uint32_t k1b,
                                                uint32_t k2a, uint32_t k2b) {
    __shared__ int slab[NB];
    __shared__ unsigned long long redn[8], redp[8];
    const int i = blockIdx.x;
    for (int t = threadIdx.x * 4; t < NB; t += 256 * 4)
        *(int4*)&slab[t] = *(const int4*)&labels[t];
    __syncthreads();
    const int Li = slab[i];
    const uint32_t base = (uint32_t)i << 12;

    unsigned long long bestn = 0ull, bestp = 0ull;
    for (int j = threadIdx.x; j < NB; j += 256) {
        uint32_t o0, o1;
        tf_enc(k2a, k2b, 0u, base + (uint32_t)j, o0, o1);
        uint32_t v = ((o0 ^ o1) >> 9) + 1u;
        unsigned long long cand =
            ((unsigned long long)v << 12) | (uint32_t)(4095 - j);
        if (slab[j] != Li) {
            if (cand > bestn) bestn = cand;
        } else {
            uint32_t p0, p1;
            tf_enc(k1a, k1b, 0u, base + (uint32_t)j, p0, p1);
            uint32_t vp = ((p0 ^ p1) >> 9) + 1u;
            unsigned long long candp =
                ((unsigned long long)vp << 12) | (uint32_t)(4095 - j);
            if (candp > bestp) bestp = candp;
        }
    }
    for (int off = 16; off; off >>= 1) {
        unsigned long long a = __shfl_down_sync(0xffffffffu, bestn, off);
        unsigned long long b = __shfl_down_sync(0xffffffffu, bestp, off);
        if (a > bestn) bestn = a;
        if (b > bestp) bestp = b;
    }
    const int warp = threadIdx.x >> 5, lane = threadIdx.x & 31;
    if (lane == 0) { redn[warp] = bestn; redp[warp] = bestp; }
    __syncthreads();
    if (threadIdx.x == 0) {
        unsigned long long bn = 0ull, bp = 0ull;
        for (int w = 0; w < 8; w++) {
            if (redn[w] > bn) bn = redn[w];
            if (redp[w] > bp) bp = redp[w];
        }
        g_neg[i] = 4095 - (int)(bn & 0xFFFu);
        g_pos[i] = 4095 - (int)(bp & 0xFFFu);
    }
}

// ------------------------- fused fp16 split + row norms ---------------------
__global__ void __launch_bounds__(256) k_prep(const float* __restrict__ F) {
    const int i = blockIdx.x, tid = threadIdx.x;
    const float4 v = *(const float4*)(F + (size_t)i * ND + tid * 4);
    float x[4] = {v.x, v.y, v.z, v.w};
    uint16_t h[4];
    float n2 = 0.f, s = 0.f;
#pragma unroll
    for (int e = 0; e < 4; e++) {
        __half hb = __float2half_rn(x[e]);
        h[e] = *(uint16_t*)&hb;
        n2 = fmaf(x[e], x[e], n2);
        s += x[e];
    }
    *(uint64_t*)(g_hi + (size_t)i * ND + tid * 4) = *(const uint64_t*)h;

    for (int off = 16; off; off >>= 1) {
        n2 += __shfl_down_sync(0xffffffffu, n2, off);
        s  += __shfl_down_sync(0xffffffffu, s,  off);
    }
    __shared__ float sn[8], ss[8];
    const int warp = tid >> 5, lane = tid & 31;
    if (lane == 0) { sn[warp] = n2; ss[warp] = s; }
    __syncthreads();
    if (tid == 0) {
        float a = 0.f, b = 0.f;
        for (int w = 0; w < 8; w++) { a += sn[w]; b += ss[w]; }
        g_t[i] = a + 2.f * F_EPS * b + (float)ND * F_EPS * F_EPS;
        g_c[i] = a - 2.f * F_EPS * b;
    }
}

// ------------------------- mma.sync GEMM helpers ----------------------------
__device__ __forceinline__ uint32_t smem_u32(const void* p) {
    uint32_t a;
    asm("{ .reg .u64 t; cvta.to.shared.u64 t, %1; cvt.u32.u64 %0, t; }"
        : "=r"(a) : "l"(p));
    return a;
}
#define LDSM4(r0, r1, r2, r3, addr)                                          \
    asm volatile("ldmatrix.sync.aligned.m8n8.x4.shared.b16 {%0,%1,%2,%3}, [%4];" \
                 : "=r"(r0), "=r"(r1), "=r"(r2), "=r"(r3) : "r"(addr))
#define MMA16816(c, a0, a1, a2, a3, b0, b1)                                  \
    asm volatile("mma.sync.aligned.m16n8k16.row.col.f32.f16.f16.f32 "        \
                 "{%0,%1,%2,%3}, {%4,%5,%6,%7}, {%8,%9}, {%0,%1,%2,%3};"     \
                 : "+f"((c)[0]), "+f"((c)[1]), "+f"((c)[2]), "+f"((c)[3])    \
                 : "r"(a0), "r"(a1), "r"(a2), "r"(a3), "r"(b0), "r"(b1))
#define CP16(saddr, gptr)                                                    \
    asm volatile("cp.async.cg.shared.global [%0], [%1], 16;"                 \
                 :: "r"(saddr), "l"(gptr) : "memory")

// smem stage: 2 tiles of 8192 B (Ahi, Bhi), 4 stages.
// Each tile: 128 rows x 64 B (32 fp16), 16B chunks swizzled c' = c ^ ((m>>1)&3).
#define STAGE_BYTES 16384
#define TILE_BYTES  8192
#define DSM_BYTES   67584   // max(4 stages = 65536, transpose 128*132*4)

// --------------- tensor-core GEMM: G = Hi * Hi^T (single product) -----------
__global__ void __launch_bounds__(256, 2) k_gemm_mma() {
    // triangle decode: bid -> (bx, by), by <= bx
    int bid = blockIdx.x;
    int bx = (int)((sqrt(8.0 * (double)bid + 1.0) - 1.0) * 0.5);
    while ((bx + 1) * (bx + 2) / 2 <= bid) bx++;
    while (bx * (bx + 1) / 2 > bid) bx--;
    int by = bid - bx * (bx + 1) / 2;

    extern __shared__ char dsm[];
    const uint32_t smemBase = smem_u32(dsm);
    const int tid = threadIdx.x;
    const int lane = tid & 31, wid = tid >> 5;
    const int wm = wid >> 2, wn = wid & 3;   // warp tile: 64(m) x 32(n)

    const uint16_t* gsrc[2];
    gsrc[0] = g_hi + (size_t)(bx * 128) * ND;   // A hi
    gsrc[1] = g_hi + (size_t)(by * 128) * ND;   // B hi

    float acc[4][4][4];
#pragma unroll
    for (int a = 0; a < 4; a++)
#pragma unroll
        for (int b = 0; b < 4; b++)
#pragma unroll
            for (int c = 0; c < 4; c++) acc[a][b][c] = 0.f;

#define LOAD_STAGE(S, KT)                                                     \
    {                                                                         \
        _Pragma("unroll")                                                     \
        for (int i = 0; i < 4; i++) {                                         \
            int idx = tid + i * 256;                                          \
            int tile = idx >> 9;                                              \
            int m = (idx >> 2) & 127;                                         \
            int c = idx & 3;                                                  \
            const uint16_t* gp = gsrc[tile] + (size_t)m * ND + (KT) + c * 8;  \
            uint32_t sa = smemBase + (uint32_t)(S) * STAGE_BYTES +            \
                          tile * TILE_BYTES + m * 64 +                        \
                          ((c ^ ((m >> 1) & 3)) * 16);                        \
            CP16(sa, gp);                                                     \
        }                                                                     \
    }

    LOAD_STAGE(0, 0)
    asm volatile("cp.async.commit_group;" ::: "memory");
    LOAD_STAGE(1, 32)
    asm volatile("cp.async.commit_group;" ::: "memory");
    LOAD_STAGE(2, 64)
    asm volatile("cp.async.commit_group;" ::: "memory");

    const int r15 = lane & 15, kh = lane >> 4;
    const uint32_t rA = (uint32_t)(wm * 64 + r15);
    const uint32_t rB = (uint32_t)(wn * 32 + r15);
    const uint32_t swA = (rA >> 1) & 3, swB = (rB >> 1) & 3;

#pragma unroll 1
    for (int kc = 0; kc < 32; kc++) {
        asm volatile("cp.async.wait_group 2;" ::: "memory");
        __syncthreads();
        // prefetch stage kc+3 (that buffer was consumed in iter kc-1)
        if (kc + 3 < 32) LOAD_STAGE((kc + 3) & 3, (kc + 3) * 32)
        asm volatile("cp.async.commit_group;" ::: "memory");

        const uint32_t sb = smemBase + (uint32_t)(kc & 3) * STAGE_BYTES;
        const uint32_t aH = sb;
        const uint32_t bH = sb + TILE_BYTES;

#pragma unroll
        for (int k16 = 0; k16 < 2; k16++) {
            const uint32_t cIdx = (uint32_t)(k16 * 2 + kh);
            const uint32_t cpA = (cIdx ^ swA) * 16u;
            const uint32_t cpB = (cIdx ^ swB) * 16u;
            // --- B fragments (2 LDSM) ---
            uint32_t bh[4][2];
            {
                uint32_t r0, r1, r2, r3;
                LDSM4(r0, r1, r2, r3, bH + rB * 64 + cpB);
                bh[0][0] = r0; bh[1][0] = r1; bh[0][1] = r2; bh[1][1] = r3;
                LDSM4(r0, r1, r2, r3, bH + (rB + 16) * 64 + cpB);
                bh[2][0] = r0; bh[3][0] = r1; bh[2][1] = r2; bh[3][1] = r3;
            }
#pragma unroll
            for (int mt = 0; mt < 4; mt++) {
                uint32_t a0, a1, a2, a3;
                LDSM4(a0, a1, a2, a3,
                      aH + (rA + (uint32_t)mt * 16) * 64 + cpA);
#pragma unroll
                for (int nt = 0; nt < 4; nt++)
                    MMA16816(acc[mt][nt], a0, a1, a2, a3, bh[nt][0], bh[nt][1]);
            }
        }
    }

    // ---------------- epilogue: direct tile + mirror via smem transpose -----
    const int r0 = bx * 128, c0 = by * 128;
    const int qr = lane >> 2, qc = 2 * (lane & 3);
#pragma unroll
    for (int mt = 0; mt < 4; mt++)
#pragma unroll
        for (int nt = 0; nt < 4; nt++) {
            int row = r0 + wm * 64 + mt * 16 + qr;
            int col = c0 + wn * 32 + nt * 8 + qc;
            float2 v01 = make_float2(acc[mt][nt][0], acc[mt][nt][1]);
            float2 v23 = make_float2(acc[mt][nt][2], acc[mt][nt][3]);
            *(float2*)&g_G[(size_t)row * NB + col] = v01;
            *(float2*)&g_G[(size_t)(row + 8) * NB + col] = v23;
        }

    if (bx != by) {
        float (*sT)[132] = (float (*)[132])dsm;   // [n][m], 128x132 floats
        __syncthreads();   // compute buffers dead; reuse smem
#pragma unroll
        for (int mt = 0; mt < 4; mt++)
#pragma unroll
            for (int nt = 0; nt < 4; nt++) {
                int rl = wm * 64 + mt * 16 + qr;
                int cl = wn * 32 + nt * 8 + qc;
                sT[cl][rl]         = acc[mt][nt][0];
                sT[cl + 1][rl]     = acc[mt][nt][1];
                sT[cl][rl + 8]     = acc[mt][nt][2];
                sT[cl + 1][rl + 8] = acc[mt][nt][3];
            }
        __syncthreads();
#pragma unroll
        for (int e = tid * 4; e < 128 * 128; e += 256 * 4) {
            int n = e >> 7, m = e & 127;
            float4 v = *(float4*)&sT[n][m];
            *(float4*)&g_G[(size_t)(c0 + n) * NB + r0 + m] = v;
        }
    }
#undef LOAD_STAGE
}

// ------------------------- loss reduction -----------------------------------
__device__ __forceinline__ float pairterm(float t, float gp, float gq,
                                          float cp, float cq) {
    float sap = fmaxf(fmaf(-2.f, gp, t + cp), 1e-12f);
    float san = fmaxf(fmaf(-2.f, gq, t + cq), 1e-12f);
    float dap, dan;
    asm("sqrt.approx.f32 %0, %1;" : "=f"(dap) : "f"(sap));
    asm("sqrt.approx.f32 %0, %1;" : "=f"(dan) : "f"(san));
    return fmaxf(dap - dan + F_MARGIN, 0.f);
}

__global__ void __launch_bounds__(256) k_loss() {
    const int i = blockIdx.x;
    const int p = g_pos[i], q = g_neg[i];
    const float cp = g_c[p], cq = g_c[q];
    const float4* Gp = (const float4*)(g_G + (size_t)p * NB);
    const float4* Gq = (const float4*)(g_G + (size_t)q * NB);
    const float4* T  = (const float4*)g_t;
    float acc = 0.f;
    for (int j = threadIdx.x; j < NB / 4; j += 256) {
        float4 gp = Gp[j], gq = Gq[j], tt = T[j];
        acc += pairterm(tt.x, gp.x, gq.x, cp, cq);
        acc += pairterm(tt.y, gp.y, gq.y, cp, cq);
        acc += pairterm(tt.z, gp.z, gq.z, cp, cq);
        acc += pairterm(tt.w, gp.w, gq.w, cp, cq);
    }
    for (int off = 16; off; off >>= 1)
        acc += __shfl_down_sync(0xffffffffu, acc, off);
    __shared__ float sa[8];
    const int warp = threadIdx.x >> 5, lane = threadIdx.x & 31;
    if (lane == 0) sa[warp] = acc;
    __syncthreads();
    if (threadIdx.x == 0) {
        float s = 0.f;
        for (int w = 0; w < 8; w++) s += sa[w];
        g_part[i] = s;
    }
}

__global__ void __launch_bounds__(256) k_final(float* __restrict__ out) {
    __shared__ double sm[256];
    double a = 0.0;
    for (int i = threadIdx.x; i < NB; i += 256) a += (double)g_part[i];
    sm[threadIdx.x] = a;
    __syncthreads();
    for (int s = 128; s; s >>= 1) {
        if (threadIdx.x < s) sm[threadIdx.x] += sm[threadIdx.x + s];
        __syncthreads();
    }
    if (threadIdx.x == 0)
        out[0] = (float)(sm[0] / (double)((size_t)NB * NB));
}

// ------------------------- launch -------------------------------------------
extern "C" void kernel_launch(void* const* d_in, const int* in_sizes, int n_in,
                              void* d_out, int out_size) {
    const float* F = (const float*)d_in[0];
    const int* labels = (const int*)d_in[1];
    float* out = (float*)d_out;

    uint32_t k1a, k1b, k2a, k2b;
    tf_enc_host(0u, 42u, 0u, 0u, k1a, k1b);
    tf_enc_host(0u, 42u, 0u, 1u, k2a, k2b);

    static bool init_done = false;
    static bool have_side = false;
    static cudaStream_t s_side;
    static cudaEvent_t ev_fork, ev_join;
    if (!init_done) {
        cudaFuncSetAttribute(k_gemm_mma,
                             cudaFuncAttributeMaxDynamicSharedMemorySize,
                             DSM_BYTES);
        have_side =
            (cudaStreamCreateWithFlags(&s_side, cudaStreamNonBlocking) ==
             cudaSuccess) &&
            (cudaEventCreateWithFlags(&ev_fork, cudaEventDisableTiming) ==
             cudaSuccess) &&
            (cudaEventCreateWithFlags(&ev_join, cudaEventDisableTiming) ==
             cudaSuccess);
        init_done = true;
    }

    if (have_side) {
        // fork: sampling (pure ALU) overlaps prep + tensor GEMM
        cudaEventRecord(ev_fork, 0);
        cudaStreamWaitEvent(s_side, ev_fork, 0);
        k_sample<<<NB, 256, 0, s_side>>>(labels, k1a, k1b, k2a, k2b);
        cudaEventRecord(ev_join, s_side);

        k_prep<<<NB, 256>>>(F);
        k_gemm_mma<<<528, 256, DSM_BYTES>>>();

        cudaStreamWaitEvent(0, ev_join, 0);   // join before loss
    } else {
        k_sample<<<NB, 256>>>(labels, k1a, k1b, k2a, k2b);
        k_prep<<<NB, 256>>>(F);
        k_gemm_mma<<<528, 256, DSM_BYTES>>>();
    }
    k_loss<<<NB, 256>>>();
    k_final<<<1, 256>>>(out);
}

// round 16
// speedup vs baseline: 1.6613x; 1.0077x over previous
#include <cuda_runtime.h>
#include <cuda_fp16.h>
#include <cstdint>

#define NB 4096
#define ND 1024
#define F_EPS 1e-6f
#define F_MARGIN 0.3f

// ------------------------- scratch (static device globals; no allocation) ---
__device__ float g_G[(size_t)NB * NB];   // gram matrix F F^T (64 MB)
__device__ float g_t[NB];
__device__ float g_c[NB];
__device__ float g_n2[NB];               // exact fp32 row norms (diag patch)
__device__ int   g_pos[NB];
__device__ int   g_neg[NB];
__device__ float g_part[NB];
__device__ __align__(16) uint16_t g_hi[(size_t)NB * ND];  // fp16 hi

// ------------------------- Threefry-2x32 (20 rounds), JAX-compatible --------
__device__ __forceinline__ uint32_t rotl_d(uint32_t x, int r) {
    return __funnelshift_l(x, x, r);
}
__device__ __forceinline__ void tf_enc(uint32_t k0, uint32_t k1,
                                       uint32_t x0, uint32_t x1,
                                       uint32_t& o0, uint32_t& o1) {
    uint32_t k2 = k0 ^ k1 ^ 0x1BD11BDAu;
    x0 += k0; x1 += k1;
#define TFR(R) { x0 += x1; x1 = rotl_d(x1, R); x1 ^= x0; }
    TFR(13) TFR(15) TFR(26) TFR(6)
    x0 += k1; x1 += k2 + 1u;
    TFR(17) TFR(29) TFR(16) TFR(24)
    x0 += k2; x1 += k0 + 2u;
    TFR(13) TFR(15) TFR(26) TFR(6)
    x0 += k0; x1 += k1 + 3u;
    TFR(17) TFR(29) TFR(16) TFR(24)
    x0 += k1; x1 += k2 + 4u;
    TFR(13) TFR(15) TFR(26) TFR(6)
    x0 += k2; x1 += k0 + 5u;
#undef TFR
    o0 = x0; o1 = x1;
}
static inline uint32_t rotl_h(uint32_t x, int r) { return (x << r) | (x >> (32 - r)); }
static void tf_enc_host(uint32_t k0, uint32_t k1, uint32_t x0, uint32_t x1,
                        uint32_t& o0, uint32_t& o1) {
    uint32_t k2 = k0 ^ k1 ^ 0x1BD11BDAu;
    x0 += k0; x1 += k1;
#define TFRH(R) { x0 += x1; x1 = rotl_h(x1, R); x1 ^= x0; }
    TFRH(13) TFRH(15) TFRH(26) TFRH(6)
    x0 += k1; x1 += k2 + 1u;
    TFRH(17) TFRH(29) TFRH(16) TFRH(24)
    x0 += k2; x1 += k0 + 2u;
    TFRH(13) TFRH(15) TFRH(26) TFRH(6)
    x0 += k0; x1 += k1 + 3u;
    TFRH(17) TFRH(29) TFRH(16) TFRH(24)
    x0 += k1; x1 += k2 + 4u;
    TFRH(13) TFRH(15) TFRH(26) TFRH(6)
    x0 += k2; x1 += k0 + 5u;
#undef TFRH
    o0 = x0; o1 = x1;
}

// ------------------------- sampling kernel ----------------------------------
__global__ void __launch_bounds__(256) k_sample(const int* __restrict__ labels,
                                                uint32_t k1a, uint32_t k1b,
                                                uint32_t k2a, uint32_t k2b) {
    __shared__ int slab[NB];
    __shared__ unsigned long long redn[8], redp[8];
    const int i = blockIdx.x;
    for (int t = threadIdx.x * 4; t < NB; t += 256 * 4)
        *(int4*)&slab[t] = *(const int4*)&labels[t];
    __syncthreads();
    const int Li = slab[i];
    const uint32_t base = (uint32_t)i << 12;

    unsigned long long bestn = 0ull, bestp = 0ull;
    for (int j = threadIdx.x; j < NB; j += 256) {
        uint32_t o0, o1;
        tf_enc(k2a, k2b, 0u, base + (uint32_t)j, o0, o1);
        uint32_t v = ((o0 ^ o1) >> 9) + 1u;
        unsigned long long cand =
            ((unsigned long long)v << 12) | (uint32_t)(4095 - j);
        if (slab[j] != Li) {
            if (cand > bestn) bestn = cand;
        } else {
            uint32_t p0, p1;
            tf_enc(k1a, k1b, 0u, base + (uint32_t)j, p0, p1);
            uint32_t vp = ((p0 ^ p1) >> 9) + 1u;
            unsigned long long candp =
                ((unsigned long long)vp << 12) | (uint32_t)(4095 - j);
            if (candp > bestp) bestp = candp;
        }
    }
    for (int off = 16; off; off >>= 1) {
        unsigned long long a = __shfl_down_sync(0xffffffffu, bestn, off);
        unsigned long long b = __shfl_down_sync(0xffffffffu, bestp, off);
        if (a > bestn) bestn = a;
        if (b > bestp) bestp = b;
    }
    const int warp = threadIdx.x >> 5, lane = threadIdx.x & 31;
    if (lane == 0) { redn[warp] = bestn; redp[warp] = bestp; }
    __syncthreads();
    if (threadIdx.x == 0) {
        unsigned long long bn = 0ull, bp = 0ull;
        for (int w = 0; w < 8; w++) {
            if (redn[w] > bn) bn = redn[w];
            if (redp[w] > bp) bp = redp[w];
        }
        g_neg[i] = 4095 - (int)(bn & 0xFFFu);
        g_pos[i] = 4095 - (int)(bp & 0xFFFu);
    }
}

// ------------------------- fused fp16 split + row norms ---------------------
__global__ void __launch_bounds__(256) k_prep(const float* __restrict__ F) {
    const int i = blockIdx.x, tid = threadIdx.x;
    const float4 v = *(const float4*)(F + (size_t)i * ND + tid * 4);
    float x[4] = {v.x, v.y, v.z, v.w};
    uint16_t h[4];
    float n2 = 0.f, s = 0.f;
#pragma unroll
    for (int e = 0; e < 4; e++) {
        __half hb = __float2half_rn(x[e]);
        h[e] = *(uint16_t*)&hb;
        n2 = fmaf(x[e], x[e], n2);
        s += x[e];
    }
    *(uint64_t*)(g_hi + (size_t)i * ND + tid * 4) = *(const uint64_t*)h;

    for (int off = 16; off; off >>= 1) {
        n2 += __shfl_down_sync(0xffffffffu, n2, off);
        s  += __shfl_down_sync(0xffffffffu, s,  off);
    }
    __shared__ float sn[8], ss[8];
    const int warp = tid >> 5, lane = tid & 31;
    if (lane == 0) { sn[warp] = n2; ss[warp] = s; }
    __syncthreads();
    if (tid == 0) {
        float a = 0.f, b = 0.f;
        for (int w = 0; w < 8; w++) { a += sn[w]; b += ss[w]; }
        g_n2[i] = a;
        g_t[i] = a + 2.f * F_EPS * b + (float)ND * F_EPS * F_EPS;
        g_c[i] = a - 2.f * F_EPS * b;
    }
}

// ---------------- diagonal patch: exact fp32 norms onto G -------------------
__global__ void __launch_bounds__(256) k_diag() {
    const int i = blockIdx.x * 256 + threadIdx.x;
    g_G[(size_t)i * NB + i] = g_n2[i];
}

// ------------------------- mma.sync GEMM helpers ----------------------------
__device__ __forceinline__ uint32_t smem_u32(const void* p) {
    uint32_t a;
    asm("{ .reg .u64 t; cvta.to.shared.u64 t, %1; cvt.u32.u64 %0, t; }"
        : "=r"(a) : "l"(p));
    return a;
}
#define LDSM4(r0, r1, r2, r3, addr)                                          \
    asm volatile("ldmatrix.sync.aligned.m8n8.x4.shared.b16 {%0,%1,%2,%3}, [%4];" \
                 : "=r"(r0), "=r"(r1), "=r"(r2), "=r"(r3) : "r"(addr))
// fp16-accumulate MMA: C/D are 2 regs (f16x2 pairs), half the acc registers
#define MMA16816H(c, a0, a1, a2, a3, b0, b1)                                 \
    asm volatile("mma.sync.aligned.m16n8k16.row.col.f16.f16.f16.f16 "        \
                 "{%0,%1}, {%2,%3,%4,%5}, {%6,%7}, {%0,%1};"                 \
                 : "+r"((c)[0]), "+r"((c)[1])                                \
                 : "r"(a0), "r"(a1), "r"(a2), "r"(a3), "r"(b0), "r"(b1))
#define CP16(saddr, gptr)                                                    \
    asm volatile("cp.async.cg.shared.global [%0], [%1], 16;"                 \
                 :: "r"(saddr), "l"(gptr) : "memory")

// smem stage: 2 tiles of 8192 B (Ahi, Bhi), 4 stages.
// Each tile: 128 rows x 64 B (32 fp16), 16B chunks swizzled c' = c ^ ((m>>1)&3).
#define STAGE_BYTES 16384
#define TILE_BYTES  8192
#define DSM_BYTES   67584   // max(4 stages = 65536, transpose 128*132*4)

// --------------- tensor-core GEMM: G = Hi * Hi^T (fp16 accumulate) ----------
__global__ void __launch_bounds__(256, 2) k_gemm_mma() {
    // triangle decode: bid -> (bx, by), by <= bx
    int bid = blockIdx.x;
    int bx = (int)((sqrt(8.0 * (double)bid + 1.0) - 1.0) * 0.5);
    while ((bx + 1) * (bx + 2) / 2 <= bid) bx++;
    while (bx * (bx + 1) / 2 > bid) bx--;
    int by = bid - bx * (bx + 1) / 2;

    extern __shared__ char dsm[];
    const uint32_t smemBase = smem_u32(dsm);
    const int tid = threadIdx.x;
    const int lane = tid & 31, wid = tid >> 5;
    const int wm = wid >> 2, wn = wid & 3;   // warp tile: 64(m) x 32(n)

    const uint16_t* gsrc[2];
    gsrc[0] = g_hi + (size_t)(bx * 128) * ND;   // A hi
    gsrc[1] = g_hi + (size_t)(by * 128) * ND;   // B hi

    uint32_t acc[4][4][2];
#pragma unroll
    for (int a = 0; a < 4; a++)
#pragma unroll
        for (int b = 0; b < 4; b++) { acc[a][b][0] = 0u; acc[a][b][1] = 0u; }

#define LOAD_STAGE(S, KT)                                                     \
    {                                                                         \
        _Pragma("unroll")                                                     \
        for (int i = 0; i < 4; i++) {                                         \
            int idx = tid + i * 256;                                          \
            int tile = idx >> 9;                                              \
            int m = (idx >> 2) & 127;                                         \
            int c = idx & 3;                                                  \
            const uint16_t* gp = gsrc[tile] + (size_t)m * ND + (KT) + c * 8;  \
            uint32_t sa = smemBase + (uint32_t)(S) * STAGE_BYTES +            \
                          tile * TILE_BYTES + m * 64 +                        \
                          ((c ^ ((m >> 1) & 3)) * 16);                        \
            CP16(sa, gp);                                                     \
        }                                                                     \
    }

    LOAD_STAGE(0, 0)
    asm volatile("cp.async.commit_group;" ::: "memory");
    LOAD_STAGE(1, 32)
    asm volatile("cp.async.commit_group;" ::: "memory");
    LOAD_STAGE(2, 64)
    asm volatile("cp.async.commit_group;" ::: "memory");

    const int r15 = lane & 15, kh = lane >> 4;
    const uint32_t rA = (uint32_t)(wm * 64 + r15);
    const uint32_t rB = (uint32_t)(wn * 32 + r15);
    const uint32_t swA = (rA >> 1) & 3, swB = (rB >> 1) & 3;

#pragma unroll 1
    for (int kc = 0; kc < 32; kc++) {
        asm volatile("cp.async.wait_group 2;" ::: "memory");
        __syncthreads();
        if (kc + 3 < 32) LOAD_STAGE((kc + 3) & 3, (kc + 3) * 32)
        asm volatile("cp.async.commit_group;" ::: "memory");

        const uint32_t sb = smemBase + (uint32_t)(kc & 3) * STAGE_BYTES;
        const uint32_t aH = sb;
        const uint32_t bH = sb + TILE_BYTES;

#pragma unroll
        for (int k16 = 0; k16 < 2; k16++) {
            const uint32_t cIdx = (uint32_t)(k16 * 2 + kh);
            const uint32_t cpA = (cIdx ^ swA) * 16u;
            const uint32_t cpB = (cIdx ^ swB) * 16u;
            uint32_t bh[4][2];
            {
                uint32_t r0, r1, r2, r3;
                LDSM4(r0, r1, r2, r3, bH + rB * 64 + cpB);
                bh[0][0] = r0; bh[1][0] = r1; bh[0][1] = r2; bh[1][1] = r3;
                LDSM4(r0, r1, r2, r3, bH + (rB + 16) * 64 + cpB);
                bh[2][0] = r0; bh[3][0] = r1; bh[2][1] = r2; bh[3][1] = r3;
            }
#pragma unroll
            for (int mt = 0; mt < 4; mt++) {
                uint32_t a0, a1, a2, a3;
                LDSM4(a0, a1, a2, a3,
                      aH + (rA + (uint32_t)mt * 16) * 64 + cpA);
#pragma unroll
                for (int nt = 0; nt < 4; nt++)
                    MMA16816H(acc[mt][nt], a0, a1, a2, a3, bh[nt][0], bh[nt][1]);
            }
        }
    }

    // ---------------- epilogue: direct tile + mirror via smem transpose -----
    const int r0 = bx * 128, c0 = by * 128;
    const int qr = lane >> 2, qc = 2 * (lane & 3);
#pragma unroll
    for (int mt = 0; mt < 4; mt++)
#pragma unroll
        for (int nt = 0; nt < 4; nt++) {
            int row = r0 + wm * 64 + mt * 16 + qr;
            int col = c0 + wn * 32 + nt * 8 + qc;
            float2 v01 = __half22float2(*(__half2*)&acc[mt][nt][0]);
            float2 v23 = __half22float2(*(__half2*)&acc[mt][nt][1]);
            *(float2*)&g_G[(size_t)row * NB + col] = v01;
            *(float2*)&g_G[(size_t)(row + 8) * NB + col] = v23;
        }

    if (bx != by) {
        float (*sT)[132] = (float (*)[132])dsm;   // [n][m], 128x132 floats
        __syncthreads();   // compute buffers dead; reuse smem
#pragma unroll
        for (int mt = 0; mt < 4; mt++)
#pragma unroll
            for (int nt = 0; nt < 4; nt++) {
                int rl = wm * 64 + mt * 16 + qr;
                int cl = wn * 32 + nt * 8 + qc;
                float2 v01 = __half22float2(*(__half2*)&acc[mt][nt][0]);
                float2 v23 = __half22float2(*(__half2*)&acc[mt][nt][1]);
                sT[cl][rl]         = v01.x;
                sT[cl + 1][rl]     = v01.y;
                sT[cl][rl + 8]     = v23.x;
                sT[cl + 1][rl + 8] = v23.y;
            }
        __syncthreads();
#pragma unroll
        for (int e = tid * 4; e < 128 * 128; e += 256 * 4) {
            int n = e >> 7, m = e & 127;
            float4 v = *(float4*)&sT[n][m];
            *(float4*)&g_G[(size_t)(c0 + n) * NB + r0 + m] = v;
        }
    }
#undef LOAD_STAGE
}

// ------------------------- loss reduction -----------------------------------
__device__ __forceinline__ float pairterm(float t, float gp, float gq,
                                          float cp, float cq) {
    float sap = fmaxf(fmaf(-2.f, gp, t + cp), 1e-12f);
    float san = fmaxf(fmaf(-2.f, gq, t + cq), 1e-12f);
    float dap, dan;
    asm("sqrt.approx.f32 %0, %1;" : "=f"(dap) : "f"(sap));
    asm("sqrt.approx.f32 %0, %1;" : "=f"(dan) : "f"(san));
    return fmaxf(dap - dan + F_MARGIN, 0.f);
}

__global__ void __launch_bounds__(256) k_loss() {
    const int i = blockIdx.x;
    const int p = g_pos[i], q = g_neg[i];
    const float cp = g_c[p], cq = g_c[q];
    const float4* Gp = (const float4*)(g_G + (size_t)p * NB);
    const float4* Gq = (const float4*)(g_G + (size_t)q * NB);
    const float4* T  = (const float4*)g_t;
    float acc = 0.f;
    for (int j = threadIdx.x; j < NB / 4; j += 256) {
        float4 gp = Gp[j], gq = Gq[j], tt = T[j];
        acc += pairterm(tt.x, gp.x, gq.x, cp, cq);
        acc += pairterm(tt.y, gp.y, gq.y, cp, cq);
        acc += pairterm(tt.z, gp.z, gq.z, cp, cq);
        acc += pairterm(tt.w, gp.w, gq.w, cp, cq);
    }
    for (int off = 16; off; off >>= 1)
        acc += __shfl_down_sync(0xffffffffu, acc, off);
    __shared__ float sa[8];
    const int warp = threadIdx.x >> 5, lane = threadIdx.x & 31;
    if (lane == 0) sa[warp] = acc;
    __syncthreads();
    if (threadIdx.x == 0) {
        float s = 0.f;
        for (int w = 0; w < 8; w++) s += sa[w];
        g_part[i] = s;
    }
}

__global__ void __launch_bounds__(256) k_final(float* __restrict__ out) {
    __shared__ double sm[256];
    double a = 0.0;
    for (int i = threadIdx.x; i < NB; i += 256) a += (double)g_part[i];
    sm[threadIdx.x] = a;
    __syncthreads();
    for (int s = 128; s; s >>= 1) {
        if (threadIdx.x < s) sm[threadIdx.x] += sm[threadIdx.x + s];
        __syncthreads();
    }
    if (threadIdx.x == 0)
        out[0] = (float)(sm[0] / (double)((size_t)NB * NB));
}

// ------------------------- launch -------------------------------------------
extern "C" void kernel_launch(void* const* d_in, const int* in_sizes, int n_in,
                              void* d_out, int out_size) {
    const float* F = (const float*)d_in[0];
    const int* labels = (const int*)d_in[1];
    float* out = (float*)d_out;

    uint32_t k1a, k1b, k2a, k2b;
    tf_enc_host(0u, 42u, 0u, 0u, k1a, k1b);
    tf_enc_host(0u, 42u, 0u, 1u, k2a, k2b);

    static bool init_done = false;
    static bool have_side = false;
    static cudaStream_t s_side;
    static cudaEvent_t ev_fork, ev_join;
    if (!init_done) {
        cudaFuncSetAttribute(k_gemm_mma,
                             cudaFuncAttributeMaxDynamicSharedMemorySize,
                             DSM_BYTES);
        have_side =
            (cudaStreamCreateWithFlags(&s_side, cudaStreamNonBlocking) ==
             cudaSuccess) &&
            (cudaEventCreateWithFlags(&ev_fork, cudaEventDisableTiming) ==
             cudaSuccess) &&
            (cudaEventCreateWithFlags(&ev_join, cudaEventDisableTiming) ==
             cudaSuccess);
        init_done = true;
    }

    if (have_side) {
        // fork: sampling (pure ALU) overlaps prep + tensor GEMM
        cudaEventRecord(ev_fork, 0);
        cudaStreamWaitEvent(s_side, ev_fork, 0);
        k_sample<<<NB, 256, 0, s_side>>>(labels, k1a, k1b, k2a, k2b);
        cudaEventRecord(ev_join, s_side);

        k_prep<<<NB, 256>>>(F);
        k_gemm_mma<<<528, 256, DSM_BYTES>>>();
        k_diag<<<16, 256>>>();

        cudaStreamWaitEvent(0, ev_join, 0);   // join before loss
    } else {
        k_sample<<<NB, 256>>>(labels, k1a, k1b, k2a, k2b);
        k_prep<<<NB, 256>>>(F);
        k_gemm_mma<<<528, 256, DSM_BYTES>>>();
        k_diag<<<16, 256>>>();
    }
    k_loss<<<NB, 256>>>();
    k_final<<<1, 256>>>(out);
}

// round 17
// speedup vs baseline: 1.7494x; 1.0530x over previous
#include <cuda_runtime.h>
#include <cuda_fp16.h>
#include <cstdint>

#define NB 4096
#define ND 1024
#define F_EPS 1e-6f
#define F_MARGIN 0.3f

// ------------------------- scratch (static device globals; no allocation) ---
__device__ __align__(16) uint16_t g_Gh[(size_t)NB * NB];  // gram fp16 (32 MB)
__device__ float g_t[NB];
__device__ float g_c[NB];
__device__ float g_n2[NB];               // exact fp32 row norms
__device__ int   g_pos[NB];
__device__ int   g_neg[NB];
__device__ float g_part[NB];
__device__ __align__(16) uint16_t g_hi[(size_t)NB * ND];  // fp16 inputs

// ------------------------- Threefry-2x32 (20 rounds), JAX-compatible --------
__device__ __forceinline__ uint32_t rotl_d(uint32_t x, int r) {
    return __funnelshift_l(x, x, r);
}
__device__ __forceinline__ void tf_enc(uint32_t k0, uint32_t k1,
                                       uint32_t x0, uint32_t x1,
                                       uint32_t& o0, uint32_t& o1) {
    uint32_t k2 = k0 ^ k1 ^ 0x1BD11BDAu;
    x0 += k0; x1 += k1;
#define TFR(R) { x0 += x1; x1 = rotl_d(x1, R); x1 ^= x0; }
    TFR(13) TFR(15) TFR(26) TFR(6)
    x0 += k1; x1 += k2 + 1u;
    TFR(17) TFR(29) TFR(16) TFR(24)
    x0 += k2; x1 += k0 + 2u;
    TFR(13) TFR(15) TFR(26) TFR(6)
    x0 += k0; x1 += k1 + 3u;
    TFR(17) TFR(29) TFR(16) TFR(24)
    x0 += k1; x1 += k2 + 4u;
    TFR(13) TFR(15) TFR(26) TFR(6)
    x0 += k2; x1 += k0 + 5u;
#undef TFR
    o0 = x0; o1 = x1;
}
static inline uint32_t rotl_h(uint32_t x, int r) { return (x << r) | (x >> (32 - r)); }
static void tf_enc_host(uint32_t k0, uint32_t k1, uint32_t x0, uint32_t x1,
                        uint32_t& o0, uint32_t& o1) {
    uint32_t k2 = k0 ^ k1 ^ 0x1BD11BDAu;
    x0 += k0; x1 += k1;
#define TFRH(R) { x0 += x1; x1 = rotl_h(x1, R); x1 ^= x0; }
    TFRH(13) TFRH(15) TFRH(26) TFRH(6)
    x0 += k1; x1 += k2 + 1u;
    TFRH(17) TFRH(29) TFRH(16) TFRH(24)
    x0 += k2; x1 += k0 + 2u;
    TFRH(13) TFRH(15) TFRH(26) TFRH(6)
    x0 += k0; x1 += k1 + 3u;
    TFRH(17) TFRH(29) TFRH(16) TFRH(24)
    x0 += k1; x1 += k2 + 4u;
    TFRH(13) TFRH(15) TFRH(26) TFRH(6)
    x0 += k2; x1 += k0 + 5u;
#undef TFRH
    o0 = x0; o1 = x1;
}

// ------------------------- sampling kernel ----------------------------------
__global__ void __launch_bounds__(256) k_sample(const int* __restrict__ labels,
                                                uint32_t k1a, uint32_t k1b,
                                                uint32_t k2a, uint32_t k2b) {
    __shared__ int slab[NB];
    __shared__ unsigned long long redn[8], redp[8];
    const int i = blockIdx.x;
    for (int t = threadIdx.x * 4; t < NB; t += 256 * 4)
        *(int4*)&slab[t] = *(const int4*)&labels[t];
    __syncthreads();
    const int Li = slab[i];
    const uint32_t base = (uint32_t)i << 12;

    unsigned long long bestn = 0ull, bestp = 0ull;
    for (int j = threadIdx.x; j < NB; j += 256) {
        uint32_t o0, o1;
        tf_enc(k2a, k2b, 0u, base + (uint32_t)j, o0, o1);
        uint32_t v = ((o0 ^ o1) >> 9) + 1u;
        unsigned long long cand =
            ((unsigned long long)v << 12) | (uint32_t)(4095 - j);
        if (slab[j] != Li) {
            if (cand > bestn) bestn = cand;
        } else {
            uint32_t p0, p1;
            tf_enc(k1a, k1b, 0u, base + (uint32_t)j, p0, p1);
            uint32_t vp = ((p0 ^ p1) >> 9) + 1u;
            unsigned long long candp =
                ((unsigned long long)vp << 12) | (uint32_t)(4095 - j);
            if (candp > bestp) bestp = candp;
        }
    }
    for (int off = 16; off; off >>= 1) {
        unsigned long long a = __shfl_down_sync(0xffffffffu, bestn, off);
        unsigned long long b = __shfl_down_sync(0xffffffffu, bestp, off);
        if (a > bestn) bestn = a;
        if (b > bestp) bestp = b;
    }
    const int warp = threadIdx.x >> 5, lane = threadIdx.x & 31;
    if (lane == 0) { redn[warp] = bestn; redp[warp] = bestp; }
    __syncthreads();
    if (threadIdx.x == 0) {
        unsigned long long bn = 0ull, bp = 0ull;
        for (int w = 0; w < 8; w++) {
            if (redn[w] > bn) bn = redn[w];
            if (redp[w] > bp) bp = redp[w];
        }
        g_neg[i] = 4095 - (int)(bn & 0xFFFu);
        g_pos[i] = 4095 - (int)(bp & 0xFFFu);
    }
}

// ------------------------- fused fp16 split + row norms ---------------------
__global__ void __launch_bounds__(256) k_prep(const float* __restrict__ F) {
    const int i = blockIdx.x, tid = threadIdx.x;
    const float4 v = *(const float4*)(F + (size_t)i * ND + tid * 4);
    float x[4] = {v.x, v.y, v.z, v.w};
    uint16_t h[4];
    float n2 = 0.f, s = 0.f;
#pragma unroll
    for (int e = 0; e < 4; e++) {
        __half hb = __float2half_rn(x[e]);
        h[e] = *(uint16_t*)&hb;
        n2 = fmaf(x[e], x[e], n2);
        s += x[e];
    }
    *(uint64_t*)(g_hi + (size_t)i * ND + tid * 4) = *(const uint64_t*)h;

    for (int off = 16; off; off >>= 1) {
        n2 += __shfl_down_sync(0xffffffffu, n2, off);
        s  += __shfl_down_sync(0xffffffffu, s,  off);
    }
    __shared__ float sn[8], ss[8];
    const int warp = tid >> 5, lane = tid & 31;
    if (lane == 0) { sn[warp] = n2; ss[warp] = s; }
    __syncthreads();
    if (tid == 0) {
        float a = 0.f, b = 0.f;
        for (int w = 0; w < 8; w++) { a += sn[w]; b += ss[w]; }
        g_n2[i] = a;
        g_t[i] = a + 2.f * F_EPS * b + (float)ND * F_EPS * F_EPS;
        g_c[i] = a - 2.f * F_EPS * b;
    }
}

// ------------------------- mma.sync GEMM helpers ----------------------------
__device__ __forceinline__ uint32_t smem_u32(const void* p) {
    uint32_t a;
    asm("{ .reg .u64 t; cvta.to.shared.u64 t, %1; cvt.u32.u64 %0, t; }"
        : "=r"(a) : "l"(p));
    return a;
}
#define LDSM4(r0, r1, r2, r3, addr)                                          \
    asm volatile("ldmatrix.sync.aligned.m8n8.x4.shared.b16 {%0,%1,%2,%3}, [%4];" \
                 : "=r"(r0), "=r"(r1), "=r"(r2), "=r"(r3) : "r"(addr))
#define MMA16816H(c, a0, a1, a2, a3, b0, b1)                                 \
    asm volatile("mma.sync.aligned.m16n8k16.row.col.f16.f16.f16.f16 "        \
                 "{%0,%1}, {%2,%3,%4,%5}, {%6,%7}, {%0,%1};"                 \
                 : "+r"((c)[0]), "+r"((c)[1])                                \
                 : "r"(a0), "r"(a1), "r"(a2), "r"(a3), "r"(b0), "r"(b1))
#define CP16(saddr, gptr)                                                    \
    asm volatile("cp.async.cg.shared.global [%0], [%1], 16;"                 \
                 :: "r"(saddr), "l"(gptr) : "memory")

#define STAGE_BYTES 16384
#define TILE_BYTES  8192
#define DSM_BYTES   65536   // 4 stages; covers half transpose (128*136*2=34816)

// --------------- tensor-core GEMM: G = Hi * Hi^T (fp16 acc, fp16 out) -------
__global__ void __launch_bounds__(256, 2) k_gemm_mma() {
    int bid = blockIdx.x;
    int bx = (int)((sqrt(8.0 * (double)bid + 1.0) - 1.0) * 0.5);
    while ((bx + 1) * (bx + 2) / 2 <= bid) bx++;
    while (bx * (bx + 1) / 2 > bid) bx--;
    int by = bid - bx * (bx + 1) / 2;

    extern __shared__ char dsm[];
    const uint32_t smemBase = smem_u32(dsm);
    const int tid = threadIdx.x;
    const int lane = tid & 31, wid = tid >> 5;
    const int wm = wid >> 2, wn = wid & 3;   // warp tile: 64(m) x 32(n)

    const uint16_t* gsrc[2];
    gsrc[0] = g_hi + (size_t)(bx * 128) * ND;
    gsrc[1] = g_hi + (size_t)(by * 128) * ND;

    uint32_t acc[4][4][2];
#pragma unroll
    for (int a = 0; a < 4; a++)
#pragma unroll
        for (int b = 0; b < 4; b++) { acc[a][b][0] = 0u; acc[a][b][1] = 0u; }

#define LOAD_STAGE(S, KT)                                                     \
    {                                                                         \
        _Pragma("unroll")                                                     \
        for (int i = 0; i < 4; i++) {                                         \
            int idx = tid + i * 256;                                          \
            int tile = idx >> 9;                                              \
            int m = (idx >> 2) & 127;                                         \
            int c = idx & 3;                                                  \
            const uint16_t* gp = gsrc[tile] + (size_t)m * ND + (KT) + c * 8;  \
            uint32_t sa = smemBase + (uint32_t)(S) * STAGE_BYTES +            \
                          tile * TILE_BYTES + m * 64 +                        \
                          ((c ^ ((m >> 1) & 3)) * 16);                        \
            CP16(sa, gp);                                                     \
        }                                                                     \
    }

    LOAD_STAGE(0, 0)
    asm volatile("cp.async.commit_group;" ::: "memory");
    LOAD_STAGE(1, 32)
    asm volatile("cp.async.commit_group;" ::: "memory");
    LOAD_STAGE(2, 64)
    asm volatile("cp.async.commit_group;" ::: "memory");

    const int r15 = lane & 15, kh = lane >> 4;
    const uint32_t rA = (uint32_t)(wm * 64 + r15);
    const uint32_t rB = (uint32_t)(wn * 32 + r15);
    const uint32_t swA = (rA >> 1) & 3, swB = (rB >> 1) & 3;

#pragma unroll 1
    for (int kc = 0; kc < 32; kc++) {
        asm volatile("cp.async.wait_group 2;" ::: "memory");
        __syncthreads();
        if (kc + 3 < 32) LOAD_STAGE((kc + 3) & 3, (kc + 3) * 32)
        asm volatile("cp.async.commit_group;" ::: "memory");

        const uint32_t sb = smemBase + (uint32_t)(kc & 3) * STAGE_BYTES;
        const uint32_t aH = sb;
        const uint32_t bH = sb + TILE_BYTES;

#pragma unroll
        for (int k16 = 0; k16 < 2; k16++) {
            const uint32_t cIdx = (uint32_t)(k16 * 2 + kh);
            const uint32_t cpA = (cIdx ^ swA) * 16u;
            const uint32_t cpB = (cIdx ^ swB) * 16u;
            uint32_t bh[4][2];
            {
                uint32_t r0, r1, r2, r3;
                LDSM4(r0, r1, r2, r3, bH + rB * 64 + cpB);
                bh[0][0] = r0; bh[1][0] = r1; bh[0][1] = r2; bh[1][1] = r3;
                LDSM4(r0, r1, r2, r3, bH + (rB + 16) * 64 + cpB);
                bh[2][0] = r0; bh[3][0] = r1; bh[2][1] = r2; bh[3][1] = r3;
            }
#pragma unroll
            for (int mt = 0; mt < 4; mt++) {
                uint32_t a0, a1, a2, a3;
                LDSM4(a0, a1, a2, a3,
                      aH + (rA + (uint32_t)mt * 16) * 64 + cpA);
#pragma unroll
                for (int nt = 0; nt < 4; nt++)
                    MMA16816H(acc[mt][nt], a0, a1, a2, a3, bh[nt][0], bh[nt][1]);
            }
        }
    }

    // ---------- epilogue: raw half2 stores + mirror via half transpose ------
    const int r0 = bx * 128, c0 = by * 128;
    const int qr = lane >> 2, qc = 2 * (lane & 3);
#pragma unroll
    for (int mt = 0; mt < 4; mt++)
#pragma unroll
        for (int nt = 0; nt < 4; nt++) {
            int row = r0 + wm * 64 + mt * 16 + qr;
            int col = c0 + wn * 32 + nt * 8 + qc;
            *(uint32_t*)&g_Gh[(size_t)row * NB + col] = acc[mt][nt][0];
            *(uint32_t*)&g_Gh[(size_t)(row + 8) * NB + col] = acc[mt][nt][1];
        }

    if (bx != by) {
        __half (*sTh)[136] = (__half (*)[136])dsm;   // [n][m], 128x136 halves
        __syncthreads();
#pragma unroll
        for (int mt = 0; mt < 4; mt++)
#pragma unroll
            for (int nt = 0; nt < 4; nt++) {
                int rl = wm * 64 + mt * 16 + qr;
                int cl = wn * 32 + nt * 8 + qc;
                __half2 h01 = *(__half2*)&acc[mt][nt][0];
                __half2 h23 = *(__half2*)&acc[mt][nt][1];
                sTh[cl][rl]         = __low2half(h01);
                sTh[cl + 1][rl]     = __high2half(h01);
                sTh[cl][rl + 8]     = __low2half(h23);
                sTh[cl + 1][rl + 8] = __high2half(h23);
            }
        __syncthreads();
#pragma unroll
        for (int it = 0; it < 8; it++) {
            int e = tid + it * 256;          // 2048 uint4 = 16384 halves
            int n = e >> 4, m = (e & 15) * 8;
            uint4 v = *(uint4*)&sTh[n][m];
            *(uint4*)&g_Gh[(size_t)(c0 + n) * NB + r0 + m] = v;
        }
    }
#undef LOAD_STAGE
}

// ------------------------- loss reduction -----------------------------------
__device__ __forceinline__ float pairterm(float t, float gp, float gq,
                                          float cp, float cq) {
    float sap = fmaxf(fmaf(-2.f, gp, t + cp), 1e-12f);
    float san = fmaxf(fmaf(-2.f, gq, t + cq), 1e-12f);
    float dap, dan;
    asm("sqrt.approx.f32 %0, %1;" : "=f"(dap) : "f"(sap));
    asm("sqrt.approx.f32 %0, %1;" : "=f"(dan) : "f"(san));
    return fmaxf(dap - dan + F_MARGIN, 0.f);
}
__device__ __forceinline__ float half_at(size_t idx) {
    __half h = *(__half*)&g_Gh[idx];
    return __half2float(h);
}

__global__ void __launch_bounds__(256) k_loss() {
    const int i = blockIdx.x;
    const int p = g_pos[i], q = g_neg[i];
    const float cp = g_c[p], cq = g_c[q];
    const uint4* GP = (const uint4*)(g_Gh + (size_t)p * NB);
    const uint4* GQ = (const uint4*)(g_Gh + (size_t)q * NB);
    const float4* T = (const float4*)g_t;
    float acc = 0.f;
    for (int j = threadIdx.x; j < NB / 8; j += 256) {
        uint4 gp = GP[j], gq = GQ[j];
        float4 ta = T[2 * j], tb = T[2 * j + 1];
        float2 p0 = __half22float2(*(__half2*)&gp.x);
        float2 p1 = __half22float2(*(__half2*)&gp.y);
        float2 p2 = __half22float2(*(__half2*)&gp.z);
        float2 p3 = __half22float2(*(__half2*)&gp.w);
        float2 q0 = __half22float2(*(__half2*)&gq.x);
        float2 q1 = __half22float2(*(__half2*)&gq.y);
        float2 q2 = __half22float2(*(__half2*)&gq.z);
        float2 q3 = __half22float2(*(__half2*)&gq.w);
        acc += pairterm(ta.x, p0.x, q0.x, cp, cq);
        acc += pairterm(ta.y, p0.y, q0.y, cp, cq);
        acc += pairterm(ta.z, p1.x, q1.x, cp, cq);
        acc += pairterm(ta.w, p1.y, q1.y, cp, cq);
        acc += pairterm(tb.x, p2.x, q2.x, cp, cq);
        acc += pairterm(tb.y, p2.y, q2.y, cp, cq);
        acc += pairterm(tb.z, p3.x, q3.x, cp, cq);
        acc += pairterm(tb.w, p3.y, q3.y, cp, cq);
    }
    for (int off = 16; off; off >>= 1)
        acc += __shfl_down_sync(0xffffffffu, acc, off);
    __shared__ float sa[8];
    const int warp = threadIdx.x >> 5, lane = threadIdx.x & 31;
    if (lane == 0) sa[warp] = acc;
    __syncthreads();
    if (threadIdx.x == 0) {
        float s = 0.f;
        for (int w = 0; w < 8; w++) s += sa[w];
        // fix the two self-pair columns (j==p, j==q): fp16 G diag is garbage
        // under the catastrophic cancellation; substitute exact fp32 norms.
        float tP = g_t[p], tQ = g_t[q];
        float gpp = half_at((size_t)p * NB + p);
        float gqp = half_at((size_t)q * NB + p);
        float gpq = half_at((size_t)p * NB + q);
        float gqq = half_at((size_t)q * NB + q);
        s += pairterm(tP, g_n2[p], gqp, cp, cq) - pairterm(tP, gpp, gqp, cp, cq);
        s += pairterm(tQ, gpq, g_n2[q], cp, cq) - pairterm(tQ, gpq, gqq, cp, cq);
        g_part[i] = s;
    }
}

__global__ void __launch_bounds__(256) k_final(float* __restrict__ out) {
    __shared__ double sm[256];
    double a = 0.0;
    for (int i = threadIdx.x; i < NB; i += 256) a += (double)g_part[i];
    sm[threadIdx.x] = a;
    __syncthreads();
    for (int s = 128; s; s >>= 1) {
        if (threadIdx.x < s) sm[threadIdx.x] += sm[threadIdx.x + s];
        __syncthreads();
    }
    if (threadIdx.x == 0)
        out[0] = (float)(sm[0] / (double)((size_t)NB * NB));
}

// ------------------------- launch -------------------------------------------
extern "C" void kernel_launch(void* const* d_in, const int* in_sizes, int n_in,
                              void* d_out, int out_size) {
    const float* F = (const float*)d_in[0];
    const int* labels = (const int*)d_in[1];
    float* out = (float*)d_out;

    uint32_t k1a, k1b, k2a, k2b;
    tf_enc_host(0u, 42u, 0u, 0u, k1a, k1b);
    tf_enc_host(0u, 42u, 0u, 1u, k2a, k2b);

    static bool init_done = false;
    static bool have_side = false;
    static cudaStream_t s_side;
    static cudaEvent_t ev_fork, ev_join;
    if (!init_done) {
        cudaFuncSetAttribute(k_gemm_mma,
                             cudaFuncAttributeMaxDynamicSharedMemorySize,
                             DSM_BYTES);
        have_side =
            (cudaStreamCreateWithFlags(&s_side, cudaStreamNonBlocking) ==
             cudaSuccess) &&
            (cudaEventCreateWithFlags(&ev_fork, cudaEventDisableTiming) ==
             cudaSuccess) &&
            (cudaEventCreateWithFlags(&ev_join, cudaEventDisableTiming) ==
             cudaSuccess);
        init_done = true;
    }

    if (have_side) {
        cudaEventRecord(ev_fork, 0);
        cudaStreamWaitEvent(s_side, ev_fork, 0);
        k_sample<<<NB, 256, 0, s_side>>>(labels, k1a, k1b, k2a, k2b);
        cudaEventRecord(ev_join, s_side);

        k_prep<<<NB, 256>>>(F);
        k_gemm_mma<<<528, 256, DSM_BYTES>>>();

        cudaStreamWaitEvent(0, ev_join, 0);
    } else {
        k_sample<<<NB, 256>>>(labels, k1a, k1b, k2a, k2b);
        k_prep<<<NB, 256>>>(F);
        k_gemm_mma<<<528, 256, DSM_BYTES>>>();
    }
    k_loss<<<NB, 256>>>();
    k_final<<<1, 256>>>(out);
}